// round 1
// baseline (speedup 1.0000x reference)
#include <cuda_runtime.h>

#define DM 2048
#define NH 16
#define HD 128
#define NB 4
#define SQ 2048
#define MT (NB*SQ)   // 8192 rows

// Scratch (device globals: no allocation allowed in kernel_launch)
__device__ float g_q[(size_t)NB*NH*SQ*HD];
__device__ float g_k[(size_t)NB*NH*SQ*HD];
__device__ float g_v[(size_t)NB*NH*SQ*HD];
__device__ float g_attn[(size_t)MT*DM];

// ---------------------------------------------------------------------------
// GEMM: out[m,e] = sum_d A[m,d] * W[e,d]   (both K-major row dots)
// 128x128 tile, 256 threads, 8x8 per thread, K-chunk 8.
// mode 0/1/2 -> write g_q/g_k/g_v in [B,H,S,HD] layout; mode 3 -> plain rows,
// and input A is taken from g_attn.
// ---------------------------------------------------------------------------
__global__ __launch_bounds__(256) void gemm128(const float* __restrict__ A,
                                               const float* __restrict__ W,
                                               float* __restrict__ outPlain,
                                               int mode)
{
    __shared__ float As[8][132];
    __shared__ float Bs[8][132];
    const int tid = threadIdx.x;
    const int m0  = blockIdx.y * 128;
    const int n0  = blockIdx.x * 128;
    const int lr  = tid >> 1;          // load row 0..127
    const int lk  = (tid & 1) * 4;     // k offset 0 or 4
    const int row = (tid >> 4) * 8;    // compute rows base
    const int col = (tid & 15) * 8;    // compute cols base

    const float* Ain = (mode == 3) ? g_attn : A;

    float acc[8][8];
#pragma unroll
    for (int i = 0; i < 8; i++)
#pragma unroll
        for (int j = 0; j < 8; j++) acc[i][j] = 0.0f;

    for (int k0 = 0; k0 < DM; k0 += 8) {
        float4 a4 = *(const float4*)(Ain + (size_t)(m0 + lr) * DM + (k0 + lk));
        float4 b4 = *(const float4*)(W   + (size_t)(n0 + lr) * DM + (k0 + lk));
        __syncthreads();
        As[lk + 0][lr] = a4.x; As[lk + 1][lr] = a4.y;
        As[lk + 2][lr] = a4.z; As[lk + 3][lr] = a4.w;
        Bs[lk + 0][lr] = b4.x; Bs[lk + 1][lr] = b4.y;
        Bs[lk + 2][lr] = b4.z; Bs[lk + 3][lr] = b4.w;
        __syncthreads();
#pragma unroll
        for (int kk = 0; kk < 8; kk++) {
            float a[8], b[8];
            *(float4*)(a)     = *(const float4*)&As[kk][row];
            *(float4*)(a + 4) = *(const float4*)&As[kk][row + 4];
            *(float4*)(b)     = *(const float4*)&Bs[kk][col];
            *(float4*)(b + 4) = *(const float4*)&Bs[kk][col + 4];
#pragma unroll
            for (int i = 0; i < 8; i++)
#pragma unroll
                for (int j = 0; j < 8; j++)
                    acc[i][j] = fmaf(a[i], b[j], acc[i][j]);
        }
    }

    if (mode == 3) {
#pragma unroll
        for (int i = 0; i < 8; i++) {
            float* dst = outPlain + (size_t)(m0 + row + i) * DM + (n0 + col);
            *(float4*)(dst)     = make_float4(acc[i][0], acc[i][1], acc[i][2], acc[i][3]);
            *(float4*)(dst + 4) = make_float4(acc[i][4], acc[i][5], acc[i][6], acc[i][7]);
        }
    } else {
        float* out = (mode == 0) ? g_q : (mode == 1) ? g_k : g_v;
        const int e = n0 + col;      // 8-wide span stays inside one head (HD=128)
        const int h = e >> 7;
        const int d = e & (HD - 1);
#pragma unroll
        for (int i = 0; i < 8; i++) {
            const int m = m0 + row + i;
            const int b = m >> 11;
            const int s = m & (SQ - 1);
            float* dst = out + (((size_t)(b * NH + h) * SQ + s) * HD + d);
            *(float4*)(dst)     = make_float4(acc[i][0], acc[i][1], acc[i][2], acc[i][3]);
            *(float4*)(dst + 4) = make_float4(acc[i][4], acc[i][5], acc[i][6], acc[i][7]);
        }
    }
}

// ---------------------------------------------------------------------------
// RoPE, in-place on g_q and g_k. One thread per (bh, s, d<64) pair.
// ---------------------------------------------------------------------------
__global__ __launch_bounds__(256) void rope_kernel(const float* __restrict__ cs,
                                                   const float* __restrict__ sn)
{
    const int idx = blockIdx.x * blockDim.x + threadIdx.x;  // < NB*NH*SQ*64
    const int d  = idx & 63;
    const int s  = (idx >> 6) & (SQ - 1);
    const int bh = idx >> 17;
    const size_t base = ((size_t)bh * SQ + s) * HD;
    const float c  = cs[s * 64 + d];
    const float si = sn[s * 64 + d];

    float q1 = g_q[base + d], q2 = g_q[base + d + 64];
    g_q[base + d]      = q1 * c - q2 * si;
    g_q[base + d + 64] = q1 * si + q2 * c;

    float k1 = g_k[base + d], k2 = g_k[base + d + 64];
    g_k[base + d]      = k1 * c - k2 * si;
    g_k[base + d + 64] = k1 * si + k2 * c;
}

// ---------------------------------------------------------------------------
// Flash attention: per (b,h), BM=64 query rows per block, stream keys BN=64.
// Q and K staged transposed (k-major rows) so score phase is pure outer
// product; P staged transposed for the PV phase.
// ---------------------------------------------------------------------------
#define BM 64
#define BN 64

struct FlashSmem {
    float Qt[HD][68];   // [k][qrow]
    float Kt[HD][68];   // [k][krow]
    float Vs[BN][HD];   // [krow][c]
    float Pt[BN][68];   // [kcol][qrow]
};

__global__ __launch_bounds__(256) void flash_kernel()
{
    extern __shared__ float smem_raw[];
    FlashSmem& sm = *reinterpret_cast<FlashSmem*>(smem_raw);

    const int tid = threadIdx.x;
    const int bh  = blockIdx.y;
    const int q0  = blockIdx.x * BM;

    const float* Q = g_q + (size_t)bh * SQ * HD;
    const float* K = g_k + (size_t)bh * SQ * HD;
    const float* V = g_v + (size_t)bh * SQ * HD;

    const int ty  = tid >> 4;      // 0..15
    const int tx  = tid & 15;      // 0..15
    const int r0  = ty * 4;        // 4 query rows (of 64)
    const int c0s = tx * 4;        // 4 score cols (of 64)
    const int c0o = tx * 8;        // 8 output cols (of 128)

    const float SCALE = 0.08838834764831845f;  // 1/sqrt(128)

    // Load Q tile transposed (once)
#pragma unroll
    for (int it = 0; it < 8; it++) {
        int linear = it * 256 + tid;           // < 2048
        int rowq = linear >> 5;                // 0..63
        int kq   = (linear & 31) * 4;          // 0..124
        float4 v4 = *(const float4*)(Q + (size_t)(q0 + rowq) * HD + kq);
        sm.Qt[kq + 0][rowq] = v4.x; sm.Qt[kq + 1][rowq] = v4.y;
        sm.Qt[kq + 2][rowq] = v4.z; sm.Qt[kq + 3][rowq] = v4.w;
    }

    float m_i[4], l_i[4], o[4][8];
#pragma unroll
    for (int i = 0; i < 4; i++) {
        m_i[i] = -1e30f;
        l_i[i] = 0.0f;
#pragma unroll
        for (int c = 0; c < 8; c++) o[i][c] = 0.0f;
    }

    for (int kv0 = 0; kv0 < SQ; kv0 += BN) {
        __syncthreads();   // prior-iter reads of Kt/Vs/Pt complete (also Qt wrt first iter)
        // Load K transposed + V natural
#pragma unroll
        for (int it = 0; it < 8; it++) {
            int linear = it * 256 + tid;
            int rowk = linear >> 5;
            int kq   = (linear & 31) * 4;
            float4 k4 = *(const float4*)(K + (size_t)(kv0 + rowk) * HD + kq);
            sm.Kt[kq + 0][rowk] = k4.x; sm.Kt[kq + 1][rowk] = k4.y;
            sm.Kt[kq + 2][rowk] = k4.z; sm.Kt[kq + 3][rowk] = k4.w;
            float4 v4 = *(const float4*)(V + (size_t)(kv0 + rowk) * HD + kq);
            *(float4*)&sm.Vs[rowk][kq] = v4;
        }
        __syncthreads();

        // Scores: s[i][j] = q_row(r0+i) . k_row(c0s+j)
        float s[4][4];
#pragma unroll
        for (int i = 0; i < 4; i++)
#pragma unroll
            for (int j = 0; j < 4; j++) s[i][j] = 0.0f;

#pragma unroll 4
        for (int k = 0; k < HD; k++) {
            float4 qa = *(const float4*)&sm.Qt[k][r0];
            float4 kb = *(const float4*)&sm.Kt[k][c0s];
            float a[4] = {qa.x, qa.y, qa.z, qa.w};
            float b[4] = {kb.x, kb.y, kb.z, kb.w};
#pragma unroll
            for (int i = 0; i < 4; i++)
#pragma unroll
                for (int j = 0; j < 4; j++)
                    s[i][j] = fmaf(a[i], b[j], s[i][j]);
        }

        // Online softmax update (row groups span tx = 16 consecutive lanes)
#pragma unroll
        for (int i = 0; i < 4; i++) {
            float mx = -1e30f;
#pragma unroll
            for (int j = 0; j < 4; j++) {
                s[i][j] *= SCALE;
                mx = fmaxf(mx, s[i][j]);
            }
#pragma unroll
            for (int off = 8; off >= 1; off >>= 1)
                mx = fmaxf(mx, __shfl_xor_sync(0xffffffffu, mx, off));
            float mnew  = fmaxf(m_i[i], mx);
            float alpha = __expf(m_i[i] - mnew);
            float rsum = 0.0f;
#pragma unroll
            for (int j = 0; j < 4; j++) {
                float p = __expf(s[i][j] - mnew);
                s[i][j] = p;
                rsum += p;
            }
#pragma unroll
            for (int off = 8; off >= 1; off >>= 1)
                rsum += __shfl_xor_sync(0xffffffffu, rsum, off);
            l_i[i] = l_i[i] * alpha + rsum;
            m_i[i] = mnew;
#pragma unroll
            for (int c = 0; c < 8; c++) o[i][c] *= alpha;
        }

        // Stage P transposed
#pragma unroll
        for (int i = 0; i < 4; i++)
#pragma unroll
            for (int j = 0; j < 4; j++)
                sm.Pt[c0s + j][r0 + i] = s[i][j];
        __syncthreads();

        // PV: o[i][c] += sum_j2 P[r][j2] * V[j2][c]
#pragma unroll 2
        for (int j2 = 0; j2 < BN; j2++) {
            float4 pa  = *(const float4*)&sm.Pt[j2][r0];
            float4 vb0 = *(const float4*)&sm.Vs[j2][c0o];
            float4 vb1 = *(const float4*)&sm.Vs[j2][c0o + 4];
            float p[4] = {pa.x, pa.y, pa.z, pa.w};
            float v[8] = {vb0.x, vb0.y, vb0.z, vb0.w, vb1.x, vb1.y, vb1.z, vb1.w};
#pragma unroll
            for (int i = 0; i < 4; i++)
#pragma unroll
                for (int c = 0; c < 8; c++)
                    o[i][c] = fmaf(p[i], v[c], o[i][c]);
        }
    }

    // Epilogue: normalize rows, write g_attn in [B,S,D] layout
    const int b = bh >> 4;
    const int h = bh & (NH - 1);
#pragma unroll
    for (int i = 0; i < 4; i++) {
        float inv = 1.0f / l_i[i];
        int sq = q0 + r0 + i;
        float* dst = g_attn + (size_t)(b * SQ + sq) * DM + h * HD + c0o;
        *(float4*)(dst)     = make_float4(o[i][0] * inv, o[i][1] * inv, o[i][2] * inv, o[i][3] * inv);
        *(float4*)(dst + 4) = make_float4(o[i][4] * inv, o[i][5] * inv, o[i][6] * inv, o[i][7] * inv);
    }
}

// ---------------------------------------------------------------------------
extern "C" void kernel_launch(void* const* d_in, const int* in_sizes, int n_in,
                              void* d_out, int out_size)
{
    (void)in_sizes; (void)n_in; (void)out_size;
    const float* x    = (const float*)d_in[0];
    const float* cosp = (const float*)d_in[1];
    const float* sinp = (const float*)d_in[2];
    const float* Wq   = (const float*)d_in[3];
    const float* Wk   = (const float*)d_in[4];
    const float* Wv   = (const float*)d_in[5];
    const float* Wo   = (const float*)d_in[6];
    float* out = (float*)d_out;

    dim3 gg(DM / 128, MT / 128, 1);   // (16, 64)

    gemm128<<<gg, 256>>>(x, Wq, nullptr, 0);
    gemm128<<<gg, 256>>>(x, Wk, nullptr, 1);
    gemm128<<<gg, 256>>>(x, Wv, nullptr, 2);

    rope_kernel<<<(NB * NH * SQ * 64) / 256, 256>>>(cosp, sinp);

    cudaFuncSetAttribute(flash_kernel,
                         cudaFuncAttributeMaxDynamicSharedMemorySize,
                         (int)sizeof(FlashSmem));
    flash_kernel<<<dim3(SQ / BM, NB * NH), 256, sizeof(FlashSmem)>>>();

    gemm128<<<gg, 256>>>(x, Wo, out, 3);
}

// round 3
// speedup vs baseline: 1.4616x; 1.4616x over previous
#include <cuda_runtime.h>
#include <cuda_bf16.h>
#include <cstdint>

#define DM 2048
#define NH 16
#define HD 128
#define NB 4
#define SQ 2048
#define MT (NB*SQ)   // 8192 rows
#define DMDM ((size_t)DM*DM)

// ---------------------------------------------------------------------------
// Scratch (device globals: no allocation allowed)
// ---------------------------------------------------------------------------
__device__ float g_q[(size_t)NB*NH*SQ*HD];
__device__ float g_k[(size_t)NB*NH*SQ*HD];
__device__ float g_v[(size_t)NB*NH*SQ*HD];
__device__ float g_attn[(size_t)MT*DM];

__device__ __nv_bfloat16 g_xh[(size_t)MT*DM];
__device__ __nv_bfloat16 g_xl[(size_t)MT*DM];
__device__ __nv_bfloat16 g_wh[(size_t)4*DM*DM];
__device__ __nv_bfloat16 g_wl[(size_t)4*DM*DM];

// ---------------------------------------------------------------------------
// Baseline-PTX helpers (NO sm_103a-gated instructions: no tcgen05/TMA)
// ---------------------------------------------------------------------------
__device__ __forceinline__ uint32_t smem_u32(const void* p) {
    uint32_t a;
    asm("{ .reg .u64 t; cvta.to.shared.u64 t, %1; cvt.u32.u64 %0, t; }" : "=r"(a) : "l"(p));
    return a;
}
__device__ __forceinline__ void cpasync16(uint32_t smem, const void* g) {
    asm volatile("cp.async.cg.shared.global [%0], [%1], 16;" :: "r"(smem), "l"(g));
}
__device__ __forceinline__ void cp_commit() { asm volatile("cp.async.commit_group;" ::: "memory"); }
template<int N> __device__ __forceinline__ void cp_wait() {
    asm volatile("cp.async.wait_group %0;" :: "n"(N) : "memory");
}
__device__ __forceinline__ void ldsm_x4(uint32_t* r, uint32_t addr) {
    asm volatile("ldmatrix.sync.aligned.m8n8.x4.shared.b16 {%0,%1,%2,%3}, [%4];"
                 : "=r"(r[0]), "=r"(r[1]), "=r"(r[2]), "=r"(r[3]) : "r"(addr));
}
__device__ __forceinline__ void mma16816(float* d, const uint32_t* a, const uint32_t* b) {
    asm volatile(
        "mma.sync.aligned.m16n8k16.row.col.f32.bf16.bf16.f32 "
        "{%0,%1,%2,%3}, {%4,%5,%6,%7}, {%8,%9}, {%0,%1,%2,%3};"
        : "+f"(d[0]), "+f"(d[1]), "+f"(d[2]), "+f"(d[3])
        : "r"(a[0]), "r"(a[1]), "r"(a[2]), "r"(a[3]), "r"(b[0]), "r"(b[1]));
}

// ---------------------------------------------------------------------------
// fp32 -> bf16 hi/lo split (elementwise, float4 vectorized)
// ---------------------------------------------------------------------------
__global__ __launch_bounds__(256) void split_kernel(const float* __restrict__ src,
                                                    __nv_bfloat16* __restrict__ hi,
                                                    __nv_bfloat16* __restrict__ lo,
                                                    int n4)
{
    int i = blockIdx.x * 256 + threadIdx.x;
    if (i >= n4) return;
    float4 v = ((const float4*)src)[i];
    float vv[4] = {v.x, v.y, v.z, v.w};
    unsigned int h[4], l[4];
#pragma unroll
    for (int j = 0; j < 4; j++) {
        __nv_bfloat16 hb = __float2bfloat16(vv[j]);
        float r = vv[j] - __bfloat162float(hb);
        __nv_bfloat16 lb = __float2bfloat16(r);
        h[j] = (unsigned int)__bfloat16_as_ushort(hb);
        l[j] = (unsigned int)__bfloat16_as_ushort(lb);
    }
    ((uint2*)hi)[i] = make_uint2(h[0] | (h[1] << 16), h[2] | (h[3] << 16));
    ((uint2*)lo)[i] = make_uint2(l[0] | (l[1] << 16), l[2] | (l[3] << 16));
}

// ---------------------------------------------------------------------------
// mma.sync bf16-split GEMM: out[m,e] = sum_d A[m,d]*W[e,d]
// CTA tile 128x128, 8 warps (warp tile 32x64), K staged 32/stage, 4-stage
// cp.async pipeline. Smem rows have 80B stride -> conflict-free ldmatrix.
// mode 0/1/2 -> g_q/g_k/g_v in [B,H,S,HD] layout; mode 3 -> plain rows.
// ---------------------------------------------------------------------------
#define KC 32
#define NSG (DM / KC)         // 64 k-stages
#define RS 80                 // smem row stride in bytes (32 bf16 + 16B pad)
#define ARR_BYTES (128 * RS)  // 10240
#define STAGE_BYTES (4 * ARR_BYTES)    // 40960: Ah, Al, Bh, Bl
#define GEMM_SMEM (4 * STAGE_BYTES)    // 163840

__device__ __forceinline__ void load_stage(uint32_t st,
                                           const __nv_bfloat16* __restrict__ aH,
                                           const __nv_bfloat16* __restrict__ aL,
                                           const __nv_bfloat16* __restrict__ bH,
                                           const __nv_bfloat16* __restrict__ bL,
                                           int m0, int n0, int k0, int tid)
{
    // 4 arrays x 128 rows x 4 chunks(16B) = 2048 chunks; 8 per thread.
    // arr is uniform per iteration: arr = it>>1.
#pragma unroll
    for (int it = 0; it < 8; it++) {
        int c   = it * 256 + tid;
        int arr = c >> 9;
        int idx = c & 511;
        int row = idx >> 2;
        int ch  = idx & 3;
        uint32_t off = st + (uint32_t)arr * ARR_BYTES + (uint32_t)row * RS + ch * 16;
        const __nv_bfloat16* src = (arr == 0) ? aH : (arr == 1) ? aL : (arr == 2) ? bH : bL;
        int grow = (arr < 2) ? (m0 + row) : (n0 + row);
        cpasync16(off, src + (size_t)grow * DM + k0 + ch * 8);
    }
}

__global__ __launch_bounds__(256, 1) void gemm_tc(const __nv_bfloat16* __restrict__ aH,
                                                  const __nv_bfloat16* __restrict__ aL,
                                                  const __nv_bfloat16* __restrict__ bH,
                                                  const __nv_bfloat16* __restrict__ bL,
                                                  float* __restrict__ outPlain,
                                                  int mode)
{
    extern __shared__ char smem_raw[];
    const uint32_t sb = smem_u32(smem_raw);
    const int tid  = threadIdx.x;
    const int lane = tid & 31;
    const int wid  = tid >> 5;
    const int m0 = blockIdx.y * 128;
    const int n0 = blockIdx.x * 128;
    const int m0w = (wid >> 1) * 32;    // warp m offset in tile
    const int n0w = (wid & 1) * 64;     // warp n offset in tile

    float acc[2][8][4];
#pragma unroll
    for (int i = 0; i < 2; i++)
#pragma unroll
        for (int j = 0; j < 8; j++)
#pragma unroll
            for (int f = 0; f < 4; f++) acc[i][j][f] = 0.0f;

    // Lane-dependent ldmatrix row offsets (bytes within an array)
    uint32_t aRow[2], bRow[4];
#pragma unroll
    for (int i = 0; i < 2; i++)
        aRow[i] = (uint32_t)(m0w + i * 16 + (lane & 15)) * RS + (((uint32_t)lane >> 4) << 4);
#pragma unroll
    for (int jj = 0; jj < 4; jj++)
        bRow[jj] = (uint32_t)(n0w + jj * 16 + (((uint32_t)lane >> 4) << 3) + (lane & 7)) * RS
                 + ((((uint32_t)lane >> 3) & 1) << 4);

    // Prologue: stages 0..2
#pragma unroll
    for (int s = 0; s < 3; s++) {
        load_stage(sb + s * STAGE_BYTES, aH, aL, bH, bL, m0, n0, s * KC, tid);
        cp_commit();
    }

    for (int s = 0; s < NSG; s++) {
        cp_wait<2>();
        __syncthreads();

        if (s + 3 < NSG)
            load_stage(sb + ((s + 3) & 3) * STAGE_BYTES, aH, aL, bH, bL, m0, n0, (s + 3) * KC, tid);
        cp_commit();

        const uint32_t st = sb + (uint32_t)(s & 3) * STAGE_BYTES;
#pragma unroll
        for (int ks = 0; ks < 2; ks++) {
            const uint32_t kb = (uint32_t)ks * 32;   // 16 bf16 = 32 bytes
            uint32_t ah[2][4], al[2][4], bh[4][4], bl[4][4];
#pragma unroll
            for (int i = 0; i < 2; i++) {
                ldsm_x4(ah[i], st + 0 * ARR_BYTES + aRow[i] + kb);
                ldsm_x4(al[i], st + 1 * ARR_BYTES + aRow[i] + kb);
            }
#pragma unroll
            for (int jj = 0; jj < 4; jj++) {
                ldsm_x4(bh[jj], st + 2 * ARR_BYTES + bRow[jj] + kb);
                ldsm_x4(bl[jj], st + 3 * ARR_BYTES + bRow[jj] + kb);
            }
#pragma unroll
            for (int i = 0; i < 2; i++)
#pragma unroll
                for (int jj = 0; jj < 4; jj++) {
                    mma16816(acc[i][2 * jj],     ah[i], &bh[jj][0]);
                    mma16816(acc[i][2 * jj + 1], ah[i], &bh[jj][2]);
                    mma16816(acc[i][2 * jj],     ah[i], &bl[jj][0]);
                    mma16816(acc[i][2 * jj + 1], ah[i], &bl[jj][2]);
                    mma16816(acc[i][2 * jj],     al[i], &bh[jj][0]);
                    mma16816(acc[i][2 * jj + 1], al[i], &bh[jj][2]);
                }
        }
    }

    // Epilogue: direct float2 stores
    const int gid = lane >> 2;
    const int tig = lane & 3;
    float* out = (mode == 0) ? g_q : (mode == 1) ? g_k : (mode == 2) ? g_v : outPlain;
    const int hh = n0 >> 7;   // whole 128-wide tile lies in one head

#pragma unroll
    for (int i = 0; i < 2; i++) {
        const int r0g = m0 + m0w + i * 16 + gid;
#pragma unroll
        for (int j = 0; j < 8; j++) {
            const int gcol = n0 + n0w + j * 8 + tig * 2;
            float2 v0 = make_float2(acc[i][j][0], acc[i][j][1]);
            float2 v1 = make_float2(acc[i][j][2], acc[i][j][3]);
            if (mode == 3) {
                *(float2*)(out + (size_t)r0g * DM + gcol)       = v0;
                *(float2*)(out + (size_t)(r0g + 8) * DM + gcol) = v1;
            } else {
                const int d = gcol - n0;
                int b0b = r0g >> 11, s0s = r0g & (SQ - 1);
                *(float2*)(out + (((size_t)(b0b * NH + hh) * SQ + s0s) * HD + d)) = v0;
                int r1g = r0g + 8;
                int b1b = r1g >> 11, s1s = r1g & (SQ - 1);
                *(float2*)(out + (((size_t)(b1b * NH + hh) * SQ + s1s) * HD + d)) = v1;
            }
        }
    }
}

// ---------------------------------------------------------------------------
// RoPE, in-place on g_q and g_k
// ---------------------------------------------------------------------------
__global__ __launch_bounds__(256) void rope_kernel(const float* __restrict__ cs,
                                                   const float* __restrict__ sn)
{
    const int idx = blockIdx.x * blockDim.x + threadIdx.x;
    const int d  = idx & 63;
    const int s  = (idx >> 6) & (SQ - 1);
    const int bh = idx >> 17;
    const size_t base = ((size_t)bh * SQ + s) * HD;
    const float c  = cs[s * 64 + d];
    const float si = sn[s * 64 + d];

    float q1 = g_q[base + d], q2 = g_q[base + d + 64];
    g_q[base + d]      = q1 * c - q2 * si;
    g_q[base + d + 64] = q1 * si + q2 * c;

    float k1 = g_k[base + d], k2 = g_k[base + d + 64];
    g_k[base + d]      = k1 * c - k2 * si;
    g_k[base + d + 64] = k1 * si + k2 * c;
}

// ---------------------------------------------------------------------------
// Flash attention (fp32) — unchanged
// ---------------------------------------------------------------------------
#define BM 64
#define BN 64

struct FlashSmem {
    float Qt[HD][68];
    float Kt[HD][68];
    float Vs[BN][HD];
    float Pt[BN][68];
};

__global__ __launch_bounds__(256) void flash_kernel()
{
    extern __shared__ float fsm_raw[];
    FlashSmem& sm = *reinterpret_cast<FlashSmem*>(fsm_raw);

    const int tid = threadIdx.x;
    const int bh  = blockIdx.y;
    const int q0  = blockIdx.x * BM;

    const float* Q = g_q + (size_t)bh * SQ * HD;
    const float* K = g_k + (size_t)bh * SQ * HD;
    const float* V = g_v + (size_t)bh * SQ * HD;

    const int ty  = tid >> 4;
    const int tx  = tid & 15;
    const int r0  = ty * 4;
    const int c0s = tx * 4;
    const int c0o = tx * 8;

    const float SCALE = 0.08838834764831845f;

#pragma unroll
    for (int it = 0; it < 8; it++) {
        int linear = it * 256 + tid;
        int rowq = linear >> 5;
        int kq   = (linear & 31) * 4;
        float4 v4 = *(const float4*)(Q + (size_t)(q0 + rowq) * HD + kq);
        sm.Qt[kq + 0][rowq] = v4.x; sm.Qt[kq + 1][rowq] = v4.y;
        sm.Qt[kq + 2][rowq] = v4.z; sm.Qt[kq + 3][rowq] = v4.w;
    }

    float m_i[4], l_i[4], o[4][8];
#pragma unroll
    for (int i = 0; i < 4; i++) {
        m_i[i] = -1e30f;
        l_i[i] = 0.0f;
#pragma unroll
        for (int c = 0; c < 8; c++) o[i][c] = 0.0f;
    }

    for (int kv0 = 0; kv0 < SQ; kv0 += BN) {
        __syncthreads();
#pragma unroll
        for (int it = 0; it < 8; it++) {
            int linear = it * 256 + tid;
            int rowk = linear >> 5;
            int kq   = (linear & 31) * 4;
            float4 k4 = *(const float4*)(K + (size_t)(kv0 + rowk) * HD + kq);
            sm.Kt[kq + 0][rowk] = k4.x; sm.Kt[kq + 1][rowk] = k4.y;
            sm.Kt[kq + 2][rowk] = k4.z; sm.Kt[kq + 3][rowk] = k4.w;
            float4 v4 = *(const float4*)(V + (size_t)(kv0 + rowk) * HD + kq);
            *(float4*)&sm.Vs[rowk][kq] = v4;
        }
        __syncthreads();

        float s[4][4];
#pragma unroll
        for (int i = 0; i < 4; i++)
#pragma unroll
            for (int j = 0; j < 4; j++) s[i][j] = 0.0f;

#pragma unroll 4
        for (int k = 0; k < HD; k++) {
            float4 qa = *(const float4*)&sm.Qt[k][r0];
            float4 kb = *(const float4*)&sm.Kt[k][c0s];
            float a[4] = {qa.x, qa.y, qa.z, qa.w};
            float b[4] = {kb.x, kb.y, kb.z, kb.w};
#pragma unroll
            for (int i = 0; i < 4; i++)
#pragma unroll
                for (int j = 0; j < 4; j++)
                    s[i][j] = fmaf(a[i], b[j], s[i][j]);
        }

#pragma unroll
        for (int i = 0; i < 4; i++) {
            float mx = -1e30f;
#pragma unroll
            for (int j = 0; j < 4; j++) {
                s[i][j] *= SCALE;
                mx = fmaxf(mx, s[i][j]);
            }
#pragma unroll
            for (int off = 8; off >= 1; off >>= 1)
                mx = fmaxf(mx, __shfl_xor_sync(0xffffffffu, mx, off));
            float mnew  = fmaxf(m_i[i], mx);
            float alpha = __expf(m_i[i] - mnew);
            float rsum = 0.0f;
#pragma unroll
            for (int j = 0; j < 4; j++) {
                float p = __expf(s[i][j] - mnew);
                s[i][j] = p;
                rsum += p;
            }
#pragma unroll
            for (int off = 8; off >= 1; off >>= 1)
                rsum += __shfl_xor_sync(0xffffffffu, rsum, off);
            l_i[i] = l_i[i] * alpha + rsum;
            m_i[i] = mnew;
#pragma unroll
            for (int c = 0; c < 8; c++) o[i][c] *= alpha;
        }

#pragma unroll
        for (int i = 0; i < 4; i++)
#pragma unroll
            for (int j = 0; j < 4; j++)
                sm.Pt[c0s + j][r0 + i] = s[i][j];
        __syncthreads();

#pragma unroll 2
        for (int j2 = 0; j2 < BN; j2++) {
            float4 pa  = *(const float4*)&sm.Pt[j2][r0];
            float4 vb0 = *(const float4*)&sm.Vs[j2][c0o];
            float4 vb1 = *(const float4*)&sm.Vs[j2][c0o + 4];
            float p[4] = {pa.x, pa.y, pa.z, pa.w};
            float v[8] = {vb0.x, vb0.y, vb0.z, vb0.w, vb1.x, vb1.y, vb1.z, vb1.w};
#pragma unroll
            for (int i = 0; i < 4; i++)
#pragma unroll
                for (int c = 0; c < 8; c++)
                    o[i][c] = fmaf(p[i], v[c], o[i][c]);
        }
    }

    const int b = bh >> 4;
    const int h = bh & (NH - 1);
#pragma unroll
    for (int i = 0; i < 4; i++) {
        float inv = 1.0f / l_i[i];
        int sq = q0 + r0 + i;
        float* dst = g_attn + (size_t)(b * SQ + sq) * DM + h * HD + c0o;
        *(float4*)(dst)     = make_float4(o[i][0] * inv, o[i][1] * inv, o[i][2] * inv, o[i][3] * inv);
        *(float4*)(dst + 4) = make_float4(o[i][4] * inv, o[i][5] * inv, o[i][6] * inv, o[i][7] * inv);
    }
}

// ---------------------------------------------------------------------------
extern "C" void kernel_launch(void* const* d_in, const int* in_sizes, int n_in,
                              void* d_out, int out_size)
{
    (void)in_sizes; (void)n_in; (void)out_size;
    const float* x    = (const float*)d_in[0];
    const float* cosp = (const float*)d_in[1];
    const float* sinp = (const float*)d_in[2];
    const float* Wq   = (const float*)d_in[3];
    const float* Wk   = (const float*)d_in[4];
    const float* Wv   = (const float*)d_in[5];
    const float* Wo   = (const float*)d_in[6];
    float* out = (float*)d_out;

    void *pxh, *pxl, *pwh, *pwl, *pattn;
    cudaGetSymbolAddress(&pxh, g_xh);
    cudaGetSymbolAddress(&pxl, g_xl);
    cudaGetSymbolAddress(&pwh, g_wh);
    cudaGetSymbolAddress(&pwl, g_wl);
    cudaGetSymbolAddress(&pattn, g_attn);
    __nv_bfloat16* xh = (__nv_bfloat16*)pxh;
    __nv_bfloat16* xl = (__nv_bfloat16*)pxl;
    __nv_bfloat16* wh = (__nv_bfloat16*)pwh;
    __nv_bfloat16* wl = (__nv_bfloat16*)pwl;
    const float* attn = (const float*)pattn;

    const int n4x = MT * DM / 4;
    const int n4w = DM * DM / 4;

    cudaFuncSetAttribute(gemm_tc, cudaFuncAttributeMaxDynamicSharedMemorySize, GEMM_SMEM);
    cudaFuncSetAttribute(flash_kernel, cudaFuncAttributeMaxDynamicSharedMemorySize,
                         (int)sizeof(FlashSmem));

    // 1. split inputs to bf16 hi/lo
    split_kernel<<<n4x / 256, 256>>>(x,  xh, xl, n4x);
    split_kernel<<<n4w / 256, 256>>>(Wq, wh + 0 * DMDM, wl + 0 * DMDM, n4w);
    split_kernel<<<n4w / 256, 256>>>(Wk, wh + 1 * DMDM, wl + 1 * DMDM, n4w);
    split_kernel<<<n4w / 256, 256>>>(Wv, wh + 2 * DMDM, wl + 2 * DMDM, n4w);
    split_kernel<<<n4w / 256, 256>>>(Wo, wh + 3 * DMDM, wl + 3 * DMDM, n4w);

    // 2. QKV projections on tensor cores (mma.sync bf16 split)
    dim3 gg(DM / 128, MT / 128);   // (16, 64)
    gemm_tc<<<gg, 256, GEMM_SMEM>>>(xh, xl, wh + 0 * DMDM, wl + 0 * DMDM, nullptr, 0);
    gemm_tc<<<gg, 256, GEMM_SMEM>>>(xh, xl, wh + 1 * DMDM, wl + 1 * DMDM, nullptr, 1);
    gemm_tc<<<gg, 256, GEMM_SMEM>>>(xh, xl, wh + 2 * DMDM, wl + 2 * DMDM, nullptr, 2);

    // 3. RoPE
    rope_kernel<<<(NB * NH * SQ * 64) / 256, 256>>>(cosp, sinp);

    // 4. attention
    flash_kernel<<<dim3(SQ / BM, NB * NH), 256, sizeof(FlashSmem)>>>();

    // 5. output projection (reuse xh/xl for attn hi/lo)
    split_kernel<<<n4x / 256, 256>>>(attn, xh, xl, n4x);
    gemm_tc<<<gg, 256, GEMM_SMEM>>>(xh, xl, wh + 3 * DMDM, wl + 3 * DMDM, out, 3);
}

// round 4
// speedup vs baseline: 3.1339x; 2.1442x over previous
#include <cuda_runtime.h>
#include <cuda_bf16.h>
#include <cstdint>

#define DM 2048
#define NH 16
#define HD 128
#define NB 4
#define SQ 2048
#define MT (NB*SQ)   // 8192 rows
#define DMDM ((size_t)DM*DM)

// ---------------------------------------------------------------------------
// Scratch (device globals)
// ---------------------------------------------------------------------------
__device__ float g_q[(size_t)NB*NH*SQ*HD];
__device__ float g_k[(size_t)NB*NH*SQ*HD];

__device__ __nv_bfloat16 g_qh[(size_t)NB*NH*SQ*HD];
__device__ __nv_bfloat16 g_ql[(size_t)NB*NH*SQ*HD];
__device__ __nv_bfloat16 g_kh[(size_t)NB*NH*SQ*HD];
__device__ __nv_bfloat16 g_kl[(size_t)NB*NH*SQ*HD];
__device__ __nv_bfloat16 g_vh[(size_t)NB*NH*SQ*HD];
__device__ __nv_bfloat16 g_vl[(size_t)NB*NH*SQ*HD];

__device__ __nv_bfloat16 g_xh[(size_t)MT*DM];
__device__ __nv_bfloat16 g_xl[(size_t)MT*DM];
__device__ __nv_bfloat16 g_wh[(size_t)4*DM*DM];
__device__ __nv_bfloat16 g_wl[(size_t)4*DM*DM];

// ---------------------------------------------------------------------------
// Baseline-PTX helpers
// ---------------------------------------------------------------------------
__device__ __forceinline__ uint32_t smem_u32(const void* p) {
    uint32_t a;
    asm("{ .reg .u64 t; cvta.to.shared.u64 t, %1; cvt.u32.u64 %0, t; }" : "=r"(a) : "l"(p));
    return a;
}
__device__ __forceinline__ void cpasync16(uint32_t smem, const void* g) {
    asm volatile("cp.async.cg.shared.global [%0], [%1], 16;" :: "r"(smem), "l"(g));
}
__device__ __forceinline__ void cp_commit() { asm volatile("cp.async.commit_group;" ::: "memory"); }
template<int N> __device__ __forceinline__ void cp_wait() {
    asm volatile("cp.async.wait_group %0;" :: "n"(N) : "memory");
}
__device__ __forceinline__ void ldsm_x4(uint32_t* r, uint32_t addr) {
    asm volatile("ldmatrix.sync.aligned.m8n8.x4.shared.b16 {%0,%1,%2,%3}, [%4];"
                 : "=r"(r[0]), "=r"(r[1]), "=r"(r[2]), "=r"(r[3]) : "r"(addr));
}
__device__ __forceinline__ void ldsm_x4_t(uint32_t* r, uint32_t addr) {
    asm volatile("ldmatrix.sync.aligned.m8n8.x4.trans.shared.b16 {%0,%1,%2,%3}, [%4];"
                 : "=r"(r[0]), "=r"(r[1]), "=r"(r[2]), "=r"(r[3]) : "r"(addr));
}
__device__ __forceinline__ void mma16816(float* d, const uint32_t* a, const uint32_t* b) {
    asm volatile(
        "mma.sync.aligned.m16n8k16.row.col.f32.bf16.bf16.f32 "
        "{%0,%1,%2,%3}, {%4,%5,%6,%7}, {%8,%9}, {%0,%1,%2,%3};"
        : "+f"(d[0]), "+f"(d[1]), "+f"(d[2]), "+f"(d[3])
        : "r"(a[0]), "r"(a[1]), "r"(a[2]), "r"(a[3]), "r"(b[0]), "r"(b[1]));
}

__device__ __forceinline__ uint32_t pack_bf16x2(__nv_bfloat16 a, __nv_bfloat16 b) {
    return (uint32_t)__bfloat16_as_ushort(a) | ((uint32_t)__bfloat16_as_ushort(b) << 16);
}
// split two floats into hi/lo packed bf16x2
__device__ __forceinline__ void bsplit2(uint32_t& hi, uint32_t& lo, float a, float b) {
    __nv_bfloat16 ah = __float2bfloat16(a);
    __nv_bfloat16 bh = __float2bfloat16(b);
    float ar = a - __bfloat162float(ah);
    float br = b - __bfloat162float(bh);
    hi = pack_bf16x2(ah, bh);
    lo = pack_bf16x2(__float2bfloat16(ar), __float2bfloat16(br));
}

// ---------------------------------------------------------------------------
// fp32 -> bf16 hi/lo split (elementwise)
// ---------------------------------------------------------------------------
__global__ __launch_bounds__(256) void split_kernel(const float* __restrict__ src,
                                                    __nv_bfloat16* __restrict__ hi,
                                                    __nv_bfloat16* __restrict__ lo,
                                                    int n4)
{
    int i = blockIdx.x * 256 + threadIdx.x;
    if (i >= n4) return;
    float4 v = ((const float4*)src)[i];
    float vv[4] = {v.x, v.y, v.z, v.w};
    unsigned int h[4], l[4];
#pragma unroll
    for (int j = 0; j < 4; j++) {
        __nv_bfloat16 hb = __float2bfloat16(vv[j]);
        float r = vv[j] - __bfloat162float(hb);
        __nv_bfloat16 lb = __float2bfloat16(r);
        h[j] = (unsigned int)__bfloat16_as_ushort(hb);
        l[j] = (unsigned int)__bfloat16_as_ushort(lb);
    }
    ((uint2*)hi)[i] = make_uint2(h[0] | (h[1] << 16), h[2] | (h[3] << 16));
    ((uint2*)lo)[i] = make_uint2(l[0] | (l[1] << 16), l[2] | (l[3] << 16));
}

// ---------------------------------------------------------------------------
// mma.sync bf16-split GEMM (as round 3), with mode 2 writing bf16 hi/lo V
// ---------------------------------------------------------------------------
#define KC 32
#define NSG (DM / KC)
#define RS 80
#define ARR_BYTES (128 * RS)
#define STAGE_BYTES (4 * ARR_BYTES)
#define GEMM_SMEM (4 * STAGE_BYTES)

__device__ __forceinline__ void load_stage(uint32_t st,
                                           const __nv_bfloat16* __restrict__ aH,
                                           const __nv_bfloat16* __restrict__ aL,
                                           const __nv_bfloat16* __restrict__ bH,
                                           const __nv_bfloat16* __restrict__ bL,
                                           int m0, int n0, int k0, int tid)
{
#pragma unroll
    for (int it = 0; it < 8; it++) {
        int c   = it * 256 + tid;
        int arr = c >> 9;
        int idx = c & 511;
        int row = idx >> 2;
        int ch  = idx & 3;
        uint32_t off = st + (uint32_t)arr * ARR_BYTES + (uint32_t)row * RS + ch * 16;
        const __nv_bfloat16* src = (arr == 0) ? aH : (arr == 1) ? aL : (arr == 2) ? bH : bL;
        int grow = (arr < 2) ? (m0 + row) : (n0 + row);
        cpasync16(off, src + (size_t)grow * DM + k0 + ch * 8);
    }
}

__global__ __launch_bounds__(256, 1) void gemm_tc(const __nv_bfloat16* __restrict__ aH,
                                                  const __nv_bfloat16* __restrict__ aL,
                                                  const __nv_bfloat16* __restrict__ bH,
                                                  const __nv_bfloat16* __restrict__ bL,
                                                  float* __restrict__ outPlain,
                                                  int mode)
{
    extern __shared__ char smem_raw[];
    const uint32_t sb = smem_u32(smem_raw);
    const int tid  = threadIdx.x;
    const int lane = tid & 31;
    const int wid  = tid >> 5;
    const int m0 = blockIdx.y * 128;
    const int n0 = blockIdx.x * 128;
    const int m0w = (wid >> 1) * 32;
    const int n0w = (wid & 1) * 64;

    float acc[2][8][4];
#pragma unroll
    for (int i = 0; i < 2; i++)
#pragma unroll
        for (int j = 0; j < 8; j++)
#pragma unroll
            for (int f = 0; f < 4; f++) acc[i][j][f] = 0.0f;

    uint32_t aRow[2], bRow[4];
#pragma unroll
    for (int i = 0; i < 2; i++)
        aRow[i] = (uint32_t)(m0w + i * 16 + (lane & 15)) * RS + (((uint32_t)lane >> 4) << 4);
#pragma unroll
    for (int jj = 0; jj < 4; jj++)
        bRow[jj] = (uint32_t)(n0w + jj * 16 + (((uint32_t)lane >> 4) << 3) + (lane & 7)) * RS
                 + ((((uint32_t)lane >> 3) & 1) << 4);

#pragma unroll
    for (int s = 0; s < 3; s++) {
        load_stage(sb + s * STAGE_BYTES, aH, aL, bH, bL, m0, n0, s * KC, tid);
        cp_commit();
    }

    for (int s = 0; s < NSG; s++) {
        cp_wait<2>();
        __syncthreads();

        if (s + 3 < NSG)
            load_stage(sb + ((s + 3) & 3) * STAGE_BYTES, aH, aL, bH, bL, m0, n0, (s + 3) * KC, tid);
        cp_commit();

        const uint32_t st = sb + (uint32_t)(s & 3) * STAGE_BYTES;
#pragma unroll
        for (int ks = 0; ks < 2; ks++) {
            const uint32_t kb = (uint32_t)ks * 32;
            uint32_t ah[2][4], al[2][4], bh[4][4], bl[4][4];
#pragma unroll
            for (int i = 0; i < 2; i++) {
                ldsm_x4(ah[i], st + 0 * ARR_BYTES + aRow[i] + kb);
                ldsm_x4(al[i], st + 1 * ARR_BYTES + aRow[i] + kb);
            }
#pragma unroll
            for (int jj = 0; jj < 4; jj++) {
                ldsm_x4(bh[jj], st + 2 * ARR_BYTES + bRow[jj] + kb);
                ldsm_x4(bl[jj], st + 3 * ARR_BYTES + bRow[jj] + kb);
            }
#pragma unroll
            for (int i = 0; i < 2; i++)
#pragma unroll
                for (int jj = 0; jj < 4; jj++) {
                    mma16816(acc[i][2 * jj],     ah[i], &bh[jj][0]);
                    mma16816(acc[i][2 * jj + 1], ah[i], &bh[jj][2]);
                    mma16816(acc[i][2 * jj],     ah[i], &bl[jj][0]);
                    mma16816(acc[i][2 * jj + 1], ah[i], &bl[jj][2]);
                    mma16816(acc[i][2 * jj],     al[i], &bh[jj][0]);
                    mma16816(acc[i][2 * jj + 1], al[i], &bh[jj][2]);
                }
        }
    }

    const int gid = lane >> 2;
    const int tig = lane & 3;
    const int hh = n0 >> 7;
    float* out = (mode == 0) ? g_q : (mode == 1) ? g_k : outPlain;

#pragma unroll
    for (int i = 0; i < 2; i++) {
        const int r0g = m0 + m0w + i * 16 + gid;
#pragma unroll
        for (int j = 0; j < 8; j++) {
            const int gcol = n0 + n0w + j * 8 + tig * 2;
            if (mode == 3) {
                *(float2*)(out + (size_t)r0g * DM + gcol) = make_float2(acc[i][j][0], acc[i][j][1]);
                *(float2*)(out + (size_t)(r0g + 8) * DM + gcol) = make_float2(acc[i][j][2], acc[i][j][3]);
            } else if (mode == 2) {
                const int d = gcol - n0;
                int b0b = r0g >> 11, s0s = r0g & (SQ - 1);
                size_t o0 = ((size_t)(b0b * NH + hh) * SQ + s0s) * HD + d;
                int r1g = r0g + 8;
                int b1b = r1g >> 11, s1s = r1g & (SQ - 1);
                size_t o1 = ((size_t)(b1b * NH + hh) * SQ + s1s) * HD + d;
                uint32_t h0, l0, h1, l1;
                bsplit2(h0, l0, acc[i][j][0], acc[i][j][1]);
                bsplit2(h1, l1, acc[i][j][2], acc[i][j][3]);
                *(uint32_t*)(g_vh + o0) = h0; *(uint32_t*)(g_vl + o0) = l0;
                *(uint32_t*)(g_vh + o1) = h1; *(uint32_t*)(g_vl + o1) = l1;
            } else {
                const int d = gcol - n0;
                int b0b = r0g >> 11, s0s = r0g & (SQ - 1);
                *(float2*)(out + (((size_t)(b0b * NH + hh) * SQ + s0s) * HD + d)) =
                    make_float2(acc[i][j][0], acc[i][j][1]);
                int r1g = r0g + 8;
                int b1b = r1g >> 11, s1s = r1g & (SQ - 1);
                *(float2*)(out + (((size_t)(b1b * NH + hh) * SQ + s1s) * HD + d)) =
                    make_float2(acc[i][j][2], acc[i][j][3]);
            }
        }
    }
}

// ---------------------------------------------------------------------------
// RoPE + bf16 hi/lo split. Q additionally pre-scaled by 1/sqrt(HD).
// ---------------------------------------------------------------------------
__device__ __forceinline__ void store_split(__nv_bfloat16* h, __nv_bfloat16* l,
                                            size_t i, float v) {
    __nv_bfloat16 hb = __float2bfloat16(v);
    h[i] = hb;
    l[i] = __float2bfloat16(v - __bfloat162float(hb));
}

__global__ __launch_bounds__(256) void rope_split(const float* __restrict__ cs,
                                                  const float* __restrict__ sn)
{
    const int idx = blockIdx.x * blockDim.x + threadIdx.x;
    const int d  = idx & 63;
    const int s  = (idx >> 6) & (SQ - 1);
    const int bh = idx >> 17;
    const size_t base = ((size_t)bh * SQ + s) * HD;
    const float c  = cs[s * 64 + d];
    const float si = sn[s * 64 + d];
    const float SCALE = 0.08838834764831845f;

    float q1 = g_q[base + d], q2 = g_q[base + d + 64];
    store_split(g_qh, g_ql, base + d,      (q1 * c - q2 * si) * SCALE);
    store_split(g_qh, g_ql, base + d + 64, (q1 * si + q2 * c) * SCALE);

    float k1 = g_k[base + d], k2 = g_k[base + d + 64];
    store_split(g_kh, g_kl, base + d,      k1 * c - k2 * si);
    store_split(g_kh, g_kl, base + d + 64, k1 * si + k2 * c);
}

// ---------------------------------------------------------------------------
// Tensor-core flash attention (bf16 split, FA2-style register P)
// CTA: (b,h) x 128 q-rows; K/V streamed in 64-row tiles, double buffered.
// Warp owns 16 q-rows. Scores: M16/N64/K128; PV: M16/N128/K64; 3 products each.
// ---------------------------------------------------------------------------
#define FRS 272u                    // smem row stride bytes (128 bf16 + 16 pad)
#define QARR 34816u                 // 128*272
#define KARR 17408u                 // 64*272
#define FST  (4u*KARR)              // stage: kh,kl,vh,vl = 69632
#define FLASH_SMEM (2u*QARR + 2u*FST)   // 208896

__device__ __forceinline__ void load_kv(uint32_t st, size_t gbase, int tid)
{
    // 4 arrays x 64 rows x 16 chunks = 4096 chunks; 16 per thread
#pragma unroll
    for (int it = 0; it < 16; it++) {
        int idx = it * 256 + tid;
        int arr = idx >> 10;            // 0 kh, 1 kl, 2 vh, 3 vl
        int r   = (idx >> 4) & 63;
        int c   = idx & 15;
        const __nv_bfloat16* src = (arr == 0) ? g_kh : (arr == 1) ? g_kl
                                 : (arr == 2) ? g_vh : g_vl;
        cpasync16(st + (uint32_t)arr * KARR + (uint32_t)r * FRS + c * 16,
                  src + gbase + (size_t)r * HD + c * 8);
    }
}

__global__ __launch_bounds__(256, 1) void flash_tc()
{
    extern __shared__ char smem_raw[];
    const uint32_t sb = smem_u32(smem_raw);
    const int tid  = threadIdx.x;
    const int lane = tid & 31;
    const int wid  = tid >> 5;
    const int bh = blockIdx.y;
    const int q0 = blockIdx.x * 128;
    const size_t qg  = ((size_t)bh * SQ + q0) * HD;
    const size_t kvg = (size_t)bh * SQ * HD;

    // ---- stage Q (hi,lo) + KV0 (group A), KV1 (group B) ----
#pragma unroll
    for (int it = 0; it < 16; it++) {
        int idx = it * 256 + tid;          // 0..4095
        int arr = idx >> 11;               // 0 qh, 1 ql
        int r   = (idx >> 4) & 127;
        int c   = idx & 15;
        const __nv_bfloat16* src = arr ? g_ql : g_qh;
        cpasync16(sb + (uint32_t)arr * QARR + (uint32_t)r * FRS + c * 16,
                  src + qg + (size_t)r * HD + c * 8);
    }
    load_kv(sb + 2u * QARR, kvg, tid);
    cp_commit();
    load_kv(sb + 2u * QARR + FST, kvg + (size_t)64 * HD, tid);
    cp_commit();

    // ldmatrix lane addresses
    const uint32_t aRowQ = (uint32_t)(wid * 16 + (lane & 15)) * FRS + (((uint32_t)lane >> 4) << 4);
    uint32_t bRowK[4];
#pragma unroll
    for (int jj = 0; jj < 4; jj++)
        bRowK[jj] = (uint32_t)(jj * 16 + (((uint32_t)lane >> 4) << 3) + (lane & 7)) * FRS
                  + ((((uint32_t)lane >> 3) & 1) << 4);
    const uint32_t vRowBase = (uint32_t)((lane & 7) + (((uint32_t)lane >> 3) & 1) * 8) * FRS
                            + (((uint32_t)lane >> 4) << 4);

    float oacc[16][4];
#pragma unroll
    for (int f = 0; f < 16; f++)
#pragma unroll
        for (int e = 0; e < 4; e++) oacc[f][e] = 0.0f;
    float m0 = -1e30f, m1 = -1e30f, l0 = 0.0f, l1 = 0.0f;

    for (int s = 0; s < SQ / 64; s++) {
        cp_wait<1>();
        __syncthreads();
        const uint32_t st = sb + 2u * QARR + (uint32_t)(s & 1) * FST;

        // ---- scores: S[16,64] = Q . K^T (3 split products) ----
        float sc[8][4];
#pragma unroll
        for (int f = 0; f < 8; f++)
#pragma unroll
            for (int e = 0; e < 4; e++) sc[f][e] = 0.0f;

#pragma unroll
        for (int ks = 0; ks < 8; ks++) {
            const uint32_t kb = (uint32_t)ks * 32;
            uint32_t qh[4], ql[4];
            ldsm_x4(qh, sb + aRowQ + kb);
            ldsm_x4(ql, sb + QARR + aRowQ + kb);
#pragma unroll
            for (int jj = 0; jj < 4; jj++) {
                uint32_t kh[4], kl[4];
                ldsm_x4(kh, st + bRowK[jj] + kb);
                ldsm_x4(kl, st + KARR + bRowK[jj] + kb);
                mma16816(sc[2 * jj],     qh, &kh[0]);
                mma16816(sc[2 * jj + 1], qh, &kh[2]);
                mma16816(sc[2 * jj],     qh, &kl[0]);
                mma16816(sc[2 * jj + 1], qh, &kl[2]);
                mma16816(sc[2 * jj],     ql, &kh[0]);
                mma16816(sc[2 * jj + 1], ql, &kh[2]);
            }
        }

        // ---- online softmax (rows g and g+8 per lane; quad reduction) ----
        float mx0 = -1e30f, mx1 = -1e30f;
#pragma unroll
        for (int f = 0; f < 8; f++) {
            mx0 = fmaxf(mx0, fmaxf(sc[f][0], sc[f][1]));
            mx1 = fmaxf(mx1, fmaxf(sc[f][2], sc[f][3]));
        }
        mx0 = fmaxf(mx0, __shfl_xor_sync(0xffffffffu, mx0, 1));
        mx0 = fmaxf(mx0, __shfl_xor_sync(0xffffffffu, mx0, 2));
        mx1 = fmaxf(mx1, __shfl_xor_sync(0xffffffffu, mx1, 1));
        mx1 = fmaxf(mx1, __shfl_xor_sync(0xffffffffu, mx1, 2));
        const float mn0 = fmaxf(m0, mx0), mn1 = fmaxf(m1, mx1);
        const float al0 = __expf(m0 - mn0), al1 = __expf(m1 - mn1);
        float rs0 = 0.0f, rs1 = 0.0f;
#pragma unroll
        for (int f = 0; f < 8; f++) {
            sc[f][0] = __expf(sc[f][0] - mn0);
            sc[f][1] = __expf(sc[f][1] - mn0);
            sc[f][2] = __expf(sc[f][2] - mn1);
            sc[f][3] = __expf(sc[f][3] - mn1);
            rs0 += sc[f][0] + sc[f][1];
            rs1 += sc[f][2] + sc[f][3];
        }
        rs0 += __shfl_xor_sync(0xffffffffu, rs0, 1);
        rs0 += __shfl_xor_sync(0xffffffffu, rs0, 2);
        rs1 += __shfl_xor_sync(0xffffffffu, rs1, 1);
        rs1 += __shfl_xor_sync(0xffffffffu, rs1, 2);
        l0 = l0 * al0 + rs0;
        l1 = l1 * al1 + rs1;
        m0 = mn0; m1 = mn1;
#pragma unroll
        for (int f = 0; f < 16; f++) {
            oacc[f][0] *= al0; oacc[f][1] *= al0;
            oacc[f][2] *= al1; oacc[f][3] *= al1;
        }

        // ---- PV: O[16,128] += P[16,64] . V[64,128] ----
#pragma unroll
        for (int t = 0; t < 4; t++) {
            uint32_t ph[4], pl[4];
            bsplit2(ph[0], pl[0], sc[2 * t][0],     sc[2 * t][1]);
            bsplit2(ph[1], pl[1], sc[2 * t][2],     sc[2 * t][3]);
            bsplit2(ph[2], pl[2], sc[2 * t + 1][0], sc[2 * t + 1][1]);
            bsplit2(ph[3], pl[3], sc[2 * t + 1][2], sc[2 * t + 1][3]);
            const uint32_t vb = vRowBase + (uint32_t)t * 16 * FRS;
#pragma unroll
            for (int dj = 0; dj < 8; dj++) {
                uint32_t vh[4], vl[4];
                ldsm_x4_t(vh, st + 2 * KARR + vb + dj * 32);
                ldsm_x4_t(vl, st + 3 * KARR + vb + dj * 32);
                mma16816(oacc[2 * dj],     ph, &vh[0]);
                mma16816(oacc[2 * dj + 1], ph, &vh[2]);
                mma16816(oacc[2 * dj],     ph, &vl[0]);
                mma16816(oacc[2 * dj + 1], ph, &vl[2]);
                mma16816(oacc[2 * dj],     pl, &vh[0]);
                mma16816(oacc[2 * dj + 1], pl, &vh[2]);
            }
        }

        __syncthreads();
        if (s + 2 < SQ / 64)
            load_kv(sb + 2u * QARR + (uint32_t)(s & 1) * FST, kvg + (size_t)(s + 2) * 64 * HD, tid);
        cp_commit();
    }

    // ---- epilogue: normalize, split to bf16 hi/lo into g_xh/g_xl ----
    const float inv0 = 1.0f / l0, inv1 = 1.0f / l1;
    const int g  = lane >> 2;
    const int c2 = (lane & 3) * 2;
    const int b = bh >> 4, h = bh & (NH - 1);
    const int rowg = q0 + wid * 16 + g;
    const size_t base0 = ((size_t)(b * SQ) + rowg) * DM + h * HD;
    const size_t base1 = base0 + (size_t)8 * DM;
#pragma unroll
    for (int f = 0; f < 16; f++) {
        const int col = f * 8 + c2;
        uint32_t h0, l0p, h1, l1p;
        bsplit2(h0, l0p, oacc[f][0] * inv0, oacc[f][1] * inv0);
        bsplit2(h1, l1p, oacc[f][2] * inv1, oacc[f][3] * inv1);
        *(uint32_t*)(g_xh + base0 + col) = h0;
        *(uint32_t*)(g_xl + base0 + col) = l0p;
        *(uint32_t*)(g_xh + base1 + col) = h1;
        *(uint32_t*)(g_xl + base1 + col) = l1p;
    }
}

// ---------------------------------------------------------------------------
extern "C" void kernel_launch(void* const* d_in, const int* in_sizes, int n_in,
                              void* d_out, int out_size)
{
    (void)in_sizes; (void)n_in; (void)out_size;
    const float* x    = (const float*)d_in[0];
    const float* cosp = (const float*)d_in[1];
    const float* sinp = (const float*)d_in[2];
    const float* Wq   = (const float*)d_in[3];
    const float* Wk   = (const float*)d_in[4];
    const float* Wv   = (const float*)d_in[5];
    const float* Wo   = (const float*)d_in[6];
    float* out = (float*)d_out;

    void *pxh, *pxl, *pwh, *pwl;
    cudaGetSymbolAddress(&pxh, g_xh);
    cudaGetSymbolAddress(&pxl, g_xl);
    cudaGetSymbolAddress(&pwh, g_wh);
    cudaGetSymbolAddress(&pwl, g_wl);
    __nv_bfloat16* xh = (__nv_bfloat16*)pxh;
    __nv_bfloat16* xl = (__nv_bfloat16*)pxl;
    __nv_bfloat16* wh = (__nv_bfloat16*)pwh;
    __nv_bfloat16* wl = (__nv_bfloat16*)pwl;

    const int n4x = MT * DM / 4;
    const int n4w = DM * DM / 4;

    cudaFuncSetAttribute(gemm_tc, cudaFuncAttributeMaxDynamicSharedMemorySize, GEMM_SMEM);
    cudaFuncSetAttribute(flash_tc, cudaFuncAttributeMaxDynamicSharedMemorySize, (int)FLASH_SMEM);

    // 1. split inputs
    split_kernel<<<n4x / 256, 256>>>(x,  xh, xl, n4x);
    split_kernel<<<n4w / 256, 256>>>(Wq, wh + 0 * DMDM, wl + 0 * DMDM, n4w);
    split_kernel<<<n4w / 256, 256>>>(Wk, wh + 1 * DMDM, wl + 1 * DMDM, n4w);
    split_kernel<<<n4w / 256, 256>>>(Wv, wh + 2 * DMDM, wl + 2 * DMDM, n4w);
    split_kernel<<<n4w / 256, 256>>>(Wo, wh + 3 * DMDM, wl + 3 * DMDM, n4w);

    // 2. QKV projections (q,k -> fp32 for RoPE; v -> bf16 hi/lo directly)
    dim3 gg(DM / 128, MT / 128);
    gemm_tc<<<gg, 256, GEMM_SMEM>>>(xh, xl, wh + 0 * DMDM, wl + 0 * DMDM, nullptr, 0);
    gemm_tc<<<gg, 256, GEMM_SMEM>>>(xh, xl, wh + 1 * DMDM, wl + 1 * DMDM, nullptr, 1);
    gemm_tc<<<gg, 256, GEMM_SMEM>>>(xh, xl, wh + 2 * DMDM, wl + 2 * DMDM, nullptr, 2);

    // 3. RoPE + split (q pre-scaled by 1/sqrt(HD))
    rope_split<<<(NB * NH * SQ * 64) / 256, 256>>>(cosp, sinp);

    // 4. tensor-core flash attention -> writes attn hi/lo into xh/xl
    flash_tc<<<dim3(SQ / 128, NB * NH), 256, FLASH_SMEM>>>();

    // 5. output projection
    gemm_tc<<<gg, 256, GEMM_SMEM>>>(xh, xl, wh + 3 * DMDM, wl + 3 * DMDM, out, 3);
}

// round 5
// speedup vs baseline: 5.0113x; 1.5991x over previous
#include <cuda_runtime.h>
#include <cuda_fp16.h>
#include <cstdint>

#define DM 2048
#define NH 16
#define HD 128
#define NB 4
#define SQ 2048
#define MT (NB*SQ)   // 8192 rows
#define DMDM ((size_t)DM*DM)

// ---------------------------------------------------------------------------
// Scratch (device globals)
// ---------------------------------------------------------------------------
__device__ float g_q[(size_t)NB*NH*SQ*HD];
__device__ float g_k[(size_t)NB*NH*SQ*HD];

__device__ __half g_qh[(size_t)NB*NH*SQ*HD];
__device__ __half g_ql[(size_t)NB*NH*SQ*HD];
__device__ __half g_k16[(size_t)NB*NH*SQ*HD];
__device__ __half g_v16[(size_t)NB*NH*SQ*HD];

__device__ __half g_xh[(size_t)MT*DM];
__device__ __half g_xl[(size_t)MT*DM];
__device__ __half g_w16[(size_t)4*DM*DM];

// ---------------------------------------------------------------------------
// Baseline-PTX helpers
// ---------------------------------------------------------------------------
__device__ __forceinline__ uint32_t smem_u32(const void* p) {
    uint32_t a;
    asm("{ .reg .u64 t; cvta.to.shared.u64 t, %1; cvt.u32.u64 %0, t; }" : "=r"(a) : "l"(p));
    return a;
}
__device__ __forceinline__ void cpasync16(uint32_t smem, const void* g) {
    asm volatile("cp.async.cg.shared.global [%0], [%1], 16;" :: "r"(smem), "l"(g));
}
__device__ __forceinline__ void cp_commit() { asm volatile("cp.async.commit_group;" ::: "memory"); }
template<int N> __device__ __forceinline__ void cp_wait() {
    asm volatile("cp.async.wait_group %0;" :: "n"(N) : "memory");
}
__device__ __forceinline__ void ldsm_x4(uint32_t* r, uint32_t addr) {
    asm volatile("ldmatrix.sync.aligned.m8n8.x4.shared.b16 {%0,%1,%2,%3}, [%4];"
                 : "=r"(r[0]), "=r"(r[1]), "=r"(r[2]), "=r"(r[3]) : "r"(addr));
}
__device__ __forceinline__ void ldsm_x4_t(uint32_t* r, uint32_t addr) {
    asm volatile("ldmatrix.sync.aligned.m8n8.x4.trans.shared.b16 {%0,%1,%2,%3}, [%4];"
                 : "=r"(r[0]), "=r"(r[1]), "=r"(r[2]), "=r"(r[3]) : "r"(addr));
}
__device__ __forceinline__ void mma16816(float* d, const uint32_t* a, const uint32_t* b) {
    asm volatile(
        "mma.sync.aligned.m16n8k16.row.col.f32.f16.f16.f32 "
        "{%0,%1,%2,%3}, {%4,%5,%6,%7}, {%8,%9}, {%0,%1,%2,%3};"
        : "+f"(d[0]), "+f"(d[1]), "+f"(d[2]), "+f"(d[3])
        : "r"(a[0]), "r"(a[1]), "r"(a[2]), "r"(a[3]), "r"(b[0]), "r"(b[1]));
}

__device__ __forceinline__ uint32_t pack_h2(__half a, __half b) {
    return (uint32_t)__half_as_ushort(a) | ((uint32_t)__half_as_ushort(b) << 16);
}
// split two floats into hi/lo packed fp16x2 (hi+lo represents input to ~2^-22)
__device__ __forceinline__ void hsplit2(uint32_t& hi, uint32_t& lo, float a, float b) {
    __half ah = __float2half_rn(a);
    __half bh = __float2half_rn(b);
    float ar = a - __half2float(ah);
    float br = b - __half2float(bh);
    hi = pack_h2(ah, bh);
    lo = pack_h2(__float2half_rn(ar), __float2half_rn(br));
}

// ---------------------------------------------------------------------------
// fp32 -> fp16 hi/lo split  and  fp32 -> fp16 round (elementwise)
// ---------------------------------------------------------------------------
__global__ __launch_bounds__(256) void split2h_kernel(const float* __restrict__ src,
                                                      __half* __restrict__ hi,
                                                      __half* __restrict__ lo,
                                                      int n4)
{
    int i = blockIdx.x * 256 + threadIdx.x;
    if (i >= n4) return;
    float4 v = ((const float4*)src)[i];
    uint32_t h0, l0, h1, l1;
    hsplit2(h0, l0, v.x, v.y);
    hsplit2(h1, l1, v.z, v.w);
    ((uint2*)hi)[i] = make_uint2(h0, h1);
    ((uint2*)lo)[i] = make_uint2(l0, l1);
}

__global__ __launch_bounds__(256) void roundh_kernel(const float* __restrict__ src,
                                                     __half* __restrict__ dst,
                                                     int n4)
{
    int i = blockIdx.x * 256 + threadIdx.x;
    if (i >= n4) return;
    float4 v = ((const float4*)src)[i];
    uint32_t p0 = pack_h2(__float2half_rn(v.x), __float2half_rn(v.y));
    uint32_t p1 = pack_h2(__float2half_rn(v.z), __float2half_rn(v.w));
    ((uint2*)dst)[i] = make_uint2(p0, p1);
}

// ---------------------------------------------------------------------------
// fp16 2-product GEMM: out[m,e] = sum_d (Ah+Al)[m,d] * B16[e,d]
// CTA tile 128x128, 8 warps (warp 32x64), KC=32, 3-stage cp.async pipeline,
// 90KB smem -> 2 CTAs/SM. mode 0/1 -> g_q/g_k fp32 ([B,H,S,HD]);
// mode 2 -> g_v16 fp16; mode 3 -> plain fp32 rows.
// ---------------------------------------------------------------------------
#define KC 32
#define NSG (DM / KC)          // 64
#define RS 80                  // smem row stride (32 fp16 = 64B + 16B pad)
#define ARR_BYTES (128 * RS)   // 10240
#define STG_BYTES (3 * ARR_BYTES)   // 30720: Ah, Al, B
#define GEMM_SMEM (3 * STG_BYTES)   // 92160

__device__ __forceinline__ void load_stage(uint32_t st,
                                           const __half* __restrict__ aH,
                                           const __half* __restrict__ aL,
                                           const __half* __restrict__ bH,
                                           int m0, int n0, int k0, int tid)
{
    // 3 arrays x 128 rows x 4 chunks(16B) = 1536 chunks; 6 per thread
#pragma unroll
    for (int it = 0; it < 6; it++) {
        int c   = it * 256 + tid;
        int arr = c >> 9;
        int idx = c & 511;
        int row = idx >> 2;
        int ch  = idx & 3;
        uint32_t off = st + (uint32_t)arr * ARR_BYTES + (uint32_t)row * RS + ch * 16;
        const __half* src = (arr == 0) ? aH : (arr == 1) ? aL : bH;
        int grow = (arr < 2) ? (m0 + row) : (n0 + row);
        cpasync16(off, src + (size_t)grow * DM + k0 + ch * 8);
    }
}

__global__ __launch_bounds__(256, 2) void gemm_tc(const __half* __restrict__ aH,
                                                  const __half* __restrict__ aL,
                                                  const __half* __restrict__ bH,
                                                  float* __restrict__ outPlain,
                                                  int mode)
{
    extern __shared__ char smem_raw[];
    const uint32_t sb = smem_u32(smem_raw);
    const int tid  = threadIdx.x;
    const int lane = tid & 31;
    const int wid  = tid >> 5;
    const int m0 = blockIdx.y * 128;
    const int n0 = blockIdx.x * 128;
    const int m0w = (wid >> 1) * 32;
    const int n0w = (wid & 1) * 64;

    float acc[2][8][4];
#pragma unroll
    for (int i = 0; i < 2; i++)
#pragma unroll
        for (int j = 0; j < 8; j++)
#pragma unroll
            for (int f = 0; f < 4; f++) acc[i][j][f] = 0.0f;

    uint32_t aRow[2], bRow[4];
#pragma unroll
    for (int i = 0; i < 2; i++)
        aRow[i] = (uint32_t)(m0w + i * 16 + (lane & 15)) * RS + (((uint32_t)lane >> 4) << 4);
#pragma unroll
    for (int jj = 0; jj < 4; jj++)
        bRow[jj] = (uint32_t)(n0w + jj * 16 + (((uint32_t)lane >> 4) << 3) + (lane & 7)) * RS
                 + ((((uint32_t)lane >> 3) & 1) << 4);

    // prologue: stages 0, 1
    load_stage(sb + 0 * STG_BYTES, aH, aL, bH, m0, n0, 0,  tid); cp_commit();
    load_stage(sb + 1 * STG_BYTES, aH, aL, bH, m0, n0, KC, tid); cp_commit();

    int cur = 0, nxt = 2;   // cur = s%3, nxt = (s+2)%3
    for (int s = 0; s < NSG; s++) {
        cp_wait<1>();
        __syncthreads();

        if (s + 2 < NSG)
            load_stage(sb + (uint32_t)nxt * STG_BYTES, aH, aL, bH, m0, n0, (s + 2) * KC, tid);
        cp_commit();

        const uint32_t st = sb + (uint32_t)cur * STG_BYTES;
#pragma unroll
        for (int ks = 0; ks < 2; ks++) {
            const uint32_t kb = (uint32_t)ks * 32;
            uint32_t ah_[2][4], al_[2][4], bh_[4][4];
#pragma unroll
            for (int i = 0; i < 2; i++) {
                ldsm_x4(ah_[i], st + aRow[i] + kb);
                ldsm_x4(al_[i], st + ARR_BYTES + aRow[i] + kb);
            }
#pragma unroll
            for (int jj = 0; jj < 4; jj++)
                ldsm_x4(bh_[jj], st + 2 * ARR_BYTES + bRow[jj] + kb);
#pragma unroll
            for (int i = 0; i < 2; i++)
#pragma unroll
                for (int jj = 0; jj < 4; jj++) {
                    mma16816(acc[i][2 * jj],     ah_[i], &bh_[jj][0]);
                    mma16816(acc[i][2 * jj + 1], ah_[i], &bh_[jj][2]);
                    mma16816(acc[i][2 * jj],     al_[i], &bh_[jj][0]);
                    mma16816(acc[i][2 * jj + 1], al_[i], &bh_[jj][2]);
                }
        }
        cur = (cur == 2) ? 0 : cur + 1;
        nxt = (nxt == 2) ? 0 : nxt + 1;
    }

    const int gid = lane >> 2;
    const int tig = lane & 3;
    const int hh = n0 >> 7;
    float* out = (mode == 0) ? g_q : (mode == 1) ? g_k : outPlain;

#pragma unroll
    for (int i = 0; i < 2; i++) {
        const int r0g = m0 + m0w + i * 16 + gid;
#pragma unroll
        for (int j = 0; j < 8; j++) {
            const int gcol = n0 + n0w + j * 8 + tig * 2;
            if (mode == 3) {
                *(float2*)(out + (size_t)r0g * DM + gcol) = make_float2(acc[i][j][0], acc[i][j][1]);
                *(float2*)(out + (size_t)(r0g + 8) * DM + gcol) = make_float2(acc[i][j][2], acc[i][j][3]);
            } else if (mode == 2) {
                const int d = gcol - n0;
                int b0b = r0g >> 11, s0s = r0g & (SQ - 1);
                size_t o0 = ((size_t)(b0b * NH + hh) * SQ + s0s) * HD + d;
                int r1g = r0g + 8;
                int b1b = r1g >> 11, s1s = r1g & (SQ - 1);
                size_t o1 = ((size_t)(b1b * NH + hh) * SQ + s1s) * HD + d;
                *(uint32_t*)(g_v16 + o0) =
                    pack_h2(__float2half_rn(acc[i][j][0]), __float2half_rn(acc[i][j][1]));
                *(uint32_t*)(g_v16 + o1) =
                    pack_h2(__float2half_rn(acc[i][j][2]), __float2half_rn(acc[i][j][3]));
            } else {
                const int d = gcol - n0;
                int b0b = r0g >> 11, s0s = r0g & (SQ - 1);
                *(float2*)(out + (((size_t)(b0b * NH + hh) * SQ + s0s) * HD + d)) =
                    make_float2(acc[i][j][0], acc[i][j][1]);
                int r1g = r0g + 8;
                int b1b = r1g >> 11, s1s = r1g & (SQ - 1);
                *(float2*)(out + (((size_t)(b1b * NH + hh) * SQ + s1s) * HD + d)) =
                    make_float2(acc[i][j][2], acc[i][j][3]);
            }
        }
    }
}

// ---------------------------------------------------------------------------
// RoPE + fp16 outputs: q -> hi/lo split (pre-scaled by 1/sqrt(HD)), k -> fp16
// ---------------------------------------------------------------------------
__device__ __forceinline__ void store_h_split(__half* h, __half* l, size_t i, float v) {
    __half hb = __float2half_rn(v);
    h[i] = hb;
    l[i] = __float2half_rn(v - __half2float(hb));
}

__global__ __launch_bounds__(256) void rope_split(const float* __restrict__ cs,
                                                  const float* __restrict__ sn)
{
    const int idx = blockIdx.x * blockDim.x + threadIdx.x;
    const int d  = idx & 63;
    const int s  = (idx >> 6) & (SQ - 1);
    const int bh = idx >> 17;
    const size_t base = ((size_t)bh * SQ + s) * HD;
    const float c  = cs[s * 64 + d];
    const float si = sn[s * 64 + d];
    const float SCALE = 0.08838834764831845f;

    float q1 = g_q[base + d], q2 = g_q[base + d + 64];
    store_h_split(g_qh, g_ql, base + d,      (q1 * c - q2 * si) * SCALE);
    store_h_split(g_qh, g_ql, base + d + 64, (q1 * si + q2 * c) * SCALE);

    float k1 = g_k[base + d], k2 = g_k[base + d + 64];
    g_k16[base + d]      = __float2half_rn(k1 * c - k2 * si);
    g_k16[base + d + 64] = __float2half_rn(k1 * si + k2 * c);
}

// ---------------------------------------------------------------------------
// Tensor-core flash attention (fp16 2-product)
// Q split hi/lo (A-operand); K, V single fp16 (B-operands); P split in regs.
// CTA: (b,h) x 128 q-rows; K/V in 64-row tiles, double buffered.
// ---------------------------------------------------------------------------
#define FRS 272u
#define QARR 34816u            // 128*272
#define KARR 17408u            // 64*272
#define FST  (2u*KARR)         // stage: k16, v16 = 34816
#define FLASH_SMEM (2u*QARR + 2u*FST)   // 139264

__device__ __forceinline__ void load_kv(uint32_t st, size_t gbase, int tid)
{
    // 2 arrays x 64 rows x 16 chunks = 2048 chunks; 8 per thread
#pragma unroll
    for (int it = 0; it < 8; it++) {
        int idx = it * 256 + tid;
        int arr = idx >> 10;            // 0 k16, 1 v16
        int r   = (idx >> 4) & 63;
        int c   = idx & 15;
        const __half* src = arr ? g_v16 : g_k16;
        cpasync16(st + (uint32_t)arr * KARR + (uint32_t)r * FRS + c * 16,
                  src + gbase + (size_t)r * HD + c * 8);
    }
}

__global__ __launch_bounds__(256, 1) void flash_tc()
{
    extern __shared__ char smem_raw[];
    const uint32_t sb = smem_u32(smem_raw);
    const int tid  = threadIdx.x;
    const int lane = tid & 31;
    const int wid  = tid >> 5;
    const int bh = blockIdx.y;
    const int q0 = blockIdx.x * 128;
    const size_t qg  = ((size_t)bh * SQ + q0) * HD;
    const size_t kvg = (size_t)bh * SQ * HD;

    // stage Q hi/lo + first two KV tiles
#pragma unroll
    for (int it = 0; it < 16; it++) {
        int idx = it * 256 + tid;
        int arr = idx >> 11;               // 0 qh, 1 ql
        int r   = (idx >> 4) & 127;
        int c   = idx & 15;
        const __half* src = arr ? g_ql : g_qh;
        cpasync16(sb + (uint32_t)arr * QARR + (uint32_t)r * FRS + c * 16,
                  src + qg + (size_t)r * HD + c * 8);
    }
    load_kv(sb + 2u * QARR, kvg, tid);
    cp_commit();
    load_kv(sb + 2u * QARR + FST, kvg + (size_t)64 * HD, tid);
    cp_commit();

    const uint32_t aRowQ = (uint32_t)(wid * 16 + (lane & 15)) * FRS + (((uint32_t)lane >> 4) << 4);
    uint32_t bRowK[4];
#pragma unroll
    for (int jj = 0; jj < 4; jj++)
        bRowK[jj] = (uint32_t)(jj * 16 + (((uint32_t)lane >> 4) << 3) + (lane & 7)) * FRS
                  + ((((uint32_t)lane >> 3) & 1) << 4);
    const uint32_t vRowBase = (uint32_t)((lane & 7) + (((uint32_t)lane >> 3) & 1) * 8) * FRS
                            + (((uint32_t)lane >> 4) << 4);

    float oacc[16][4];
#pragma unroll
    for (int f = 0; f < 16; f++)
#pragma unroll
        for (int e = 0; e < 4; e++) oacc[f][e] = 0.0f;
    float m0 = -1e30f, m1 = -1e30f, l0 = 0.0f, l1 = 0.0f;

    for (int s = 0; s < SQ / 64; s++) {
        cp_wait<1>();
        __syncthreads();
        const uint32_t st = sb + 2u * QARR + (uint32_t)(s & 1) * FST;

        // scores: S[16,64] = (Qh+Ql) . K^T
        float sc[8][4];
#pragma unroll
        for (int f = 0; f < 8; f++)
#pragma unroll
            for (int e = 0; e < 4; e++) sc[f][e] = 0.0f;

#pragma unroll
        for (int ks = 0; ks < 8; ks++) {
            const uint32_t kb = (uint32_t)ks * 32;
            uint32_t qh_[4], ql_[4];
            ldsm_x4(qh_, sb + aRowQ + kb);
            ldsm_x4(ql_, sb + QARR + aRowQ + kb);
#pragma unroll
            for (int jj = 0; jj < 4; jj++) {
                uint32_t kh_[4];
                ldsm_x4(kh_, st + bRowK[jj] + kb);
                mma16816(sc[2 * jj],     qh_, &kh_[0]);
                mma16816(sc[2 * jj + 1], qh_, &kh_[2]);
                mma16816(sc[2 * jj],     ql_, &kh_[0]);
                mma16816(sc[2 * jj + 1], ql_, &kh_[2]);
            }
        }

        // online softmax
        float mx0 = -1e30f, mx1 = -1e30f;
#pragma unroll
        for (int f = 0; f < 8; f++) {
            mx0 = fmaxf(mx0, fmaxf(sc[f][0], sc[f][1]));
            mx1 = fmaxf(mx1, fmaxf(sc[f][2], sc[f][3]));
        }
        mx0 = fmaxf(mx0, __shfl_xor_sync(0xffffffffu, mx0, 1));
        mx0 = fmaxf(mx0, __shfl_xor_sync(0xffffffffu, mx0, 2));
        mx1 = fmaxf(mx1, __shfl_xor_sync(0xffffffffu, mx1, 1));
        mx1 = fmaxf(mx1, __shfl_xor_sync(0xffffffffu, mx1, 2));
        const float mn0 = fmaxf(m0, mx0), mn1 = fmaxf(m1, mx1);
        const float al0 = __expf(m0 - mn0), al1 = __expf(m1 - mn1);
        float rs0 = 0.0f, rs1 = 0.0f;
#pragma unroll
        for (int f = 0; f < 8; f++) {
            sc[f][0] = __expf(sc[f][0] - mn0);
            sc[f][1] = __expf(sc[f][1] - mn0);
            sc[f][2] = __expf(sc[f][2] - mn1);
            sc[f][3] = __expf(sc[f][3] - mn1);
            rs0 += sc[f][0] + sc[f][1];
            rs1 += sc[f][2] + sc[f][3];
        }
        rs0 += __shfl_xor_sync(0xffffffffu, rs0, 1);
        rs0 += __shfl_xor_sync(0xffffffffu, rs0, 2);
        rs1 += __shfl_xor_sync(0xffffffffu, rs1, 1);
        rs1 += __shfl_xor_sync(0xffffffffu, rs1, 2);
        l0 = l0 * al0 + rs0;
        l1 = l1 * al1 + rs1;
        m0 = mn0; m1 = mn1;
#pragma unroll
        for (int f = 0; f < 16; f++) {
            oacc[f][0] *= al0; oacc[f][1] *= al0;
            oacc[f][2] *= al1; oacc[f][3] *= al1;
        }

        // PV: O[16,128] += (Ph+Pl) . V[64,128]
#pragma unroll
        for (int t = 0; t < 4; t++) {
            uint32_t ph[4], pl[4];
            hsplit2(ph[0], pl[0], sc[2 * t][0],     sc[2 * t][1]);
            hsplit2(ph[1], pl[1], sc[2 * t][2],     sc[2 * t][3]);
            hsplit2(ph[2], pl[2], sc[2 * t + 1][0], sc[2 * t + 1][1]);
            hsplit2(ph[3], pl[3], sc[2 * t + 1][2], sc[2 * t + 1][3]);
            const uint32_t vb = vRowBase + (uint32_t)t * 16 * FRS;
#pragma unroll
            for (int dj = 0; dj < 8; dj++) {
                uint32_t vh_[4];
                ldsm_x4_t(vh_, st + KARR + vb + dj * 32);
                mma16816(oacc[2 * dj],     ph, &vh_[0]);
                mma16816(oacc[2 * dj + 1], ph, &vh_[2]);
                mma16816(oacc[2 * dj],     pl, &vh_[0]);
                mma16816(oacc[2 * dj + 1], pl, &vh_[2]);
            }
        }

        __syncthreads();
        if (s + 2 < SQ / 64)
            load_kv(sb + 2u * QARR + (uint32_t)(s & 1) * FST, kvg + (size_t)(s + 2) * 64 * HD, tid);
        cp_commit();
    }

    // epilogue: normalize, split to fp16 hi/lo into g_xh/g_xl (Wo A-operand)
    const float inv0 = 1.0f / l0, inv1 = 1.0f / l1;
    const int g  = lane >> 2;
    const int c2 = (lane & 3) * 2;
    const int b = bh >> 4, h = bh & (NH - 1);
    const int rowg = q0 + wid * 16 + g;
    const size_t base0 = ((size_t)(b * SQ) + rowg) * DM + h * HD;
    const size_t base1 = base0 + (size_t)8 * DM;
#pragma unroll
    for (int f = 0; f < 16; f++) {
        const int col = f * 8 + c2;
        uint32_t h0, l0p, h1, l1p;
        hsplit2(h0, l0p, oacc[f][0] * inv0, oacc[f][1] * inv0);
        hsplit2(h1, l1p, oacc[f][2] * inv1, oacc[f][3] * inv1);
        *(uint32_t*)(g_xh + base0 + col) = h0;
        *(uint32_t*)(g_xl + base0 + col) = l0p;
        *(uint32_t*)(g_xh + base1 + col) = h1;
        *(uint32_t*)(g_xl + base1 + col) = l1p;
    }
}

// ---------------------------------------------------------------------------
extern "C" void kernel_launch(void* const* d_in, const int* in_sizes, int n_in,
                              void* d_out, int out_size)
{
    (void)in_sizes; (void)n_in; (void)out_size;
    const float* x    = (const float*)d_in[0];
    const float* cosp = (const float*)d_in[1];
    const float* sinp = (const float*)d_in[2];
    const float* Wq   = (const float*)d_in[3];
    const float* Wk   = (const float*)d_in[4];
    const float* Wv   = (const float*)d_in[5];
    const float* Wo   = (const float*)d_in[6];
    float* out = (float*)d_out;

    void *pxh, *pxl, *pw;
    cudaGetSymbolAddress(&pxh, g_xh);
    cudaGetSymbolAddress(&pxl, g_xl);
    cudaGetSymbolAddress(&pw,  g_w16);
    __half* xh  = (__half*)pxh;
    __half* xl  = (__half*)pxl;
    __half* w16 = (__half*)pw;

    const int n4x = MT * DM / 4;
    const int n4w = DM * DM / 4;

    cudaFuncSetAttribute(gemm_tc, cudaFuncAttributeMaxDynamicSharedMemorySize, GEMM_SMEM);
    cudaFuncSetAttribute(flash_tc, cudaFuncAttributeMaxDynamicSharedMemorySize, (int)FLASH_SMEM);

    // 1. precision prep: x -> hi/lo fp16; weights -> fp16
    split2h_kernel<<<n4x / 256, 256>>>(x, xh, xl, n4x);
    roundh_kernel<<<n4w / 256, 256>>>(Wq, w16 + 0 * DMDM, n4w);
    roundh_kernel<<<n4w / 256, 256>>>(Wk, w16 + 1 * DMDM, n4w);
    roundh_kernel<<<n4w / 256, 256>>>(Wv, w16 + 2 * DMDM, n4w);
    roundh_kernel<<<n4w / 256, 256>>>(Wo, w16 + 3 * DMDM, n4w);

    // 2. QKV projections (q,k -> fp32 for RoPE; v -> fp16 directly)
    dim3 gg(DM / 128, MT / 128);
    gemm_tc<<<gg, 256, GEMM_SMEM>>>(xh, xl, w16 + 0 * DMDM, nullptr, 0);
    gemm_tc<<<gg, 256, GEMM_SMEM>>>(xh, xl, w16 + 1 * DMDM, nullptr, 1);
    gemm_tc<<<gg, 256, GEMM_SMEM>>>(xh, xl, w16 + 2 * DMDM, nullptr, 2);

    // 3. RoPE + fp16 conversion (q pre-scaled by 1/sqrt(HD))
    rope_split<<<(NB * NH * SQ * 64) / 256, 256>>>(cosp, sinp);

    // 4. flash attention -> writes attn hi/lo into xh/xl
    flash_tc<<<dim3(SQ / 128, NB * NH), 256, FLASH_SMEM>>>();

    // 5. output projection
    gemm_tc<<<gg, 256, GEMM_SMEM>>>(xh, xl, w16 + 3 * DMDM, out, 3);
}

// round 6
// speedup vs baseline: 5.8501x; 1.1674x over previous
#include <cuda_runtime.h>
#include <cuda_fp16.h>
#include <cstdint>

#define DM 2048
#define NH 16
#define HD 128
#define NB 4
#define SQ 2048
#define MT (NB*SQ)   // 8192 rows
#define DMDM ((size_t)DM*DM)

// ---------------------------------------------------------------------------
// Scratch (device globals)
// ---------------------------------------------------------------------------
__device__ float g_q[(size_t)NB*NH*SQ*HD];
__device__ float g_k[(size_t)NB*NH*SQ*HD];

__device__ __half g_q16[(size_t)NB*NH*SQ*HD];
__device__ __half g_k16[(size_t)NB*NH*SQ*HD];
__device__ __half g_v16[(size_t)NB*NH*SQ*HD];

__device__ __half g_xh[(size_t)MT*DM];
__device__ __half g_xl[(size_t)MT*DM];
__device__ __half g_w16[(size_t)4*DM*DM];

// ---------------------------------------------------------------------------
// Baseline-PTX helpers
// ---------------------------------------------------------------------------
__device__ __forceinline__ uint32_t smem_u32(const void* p) {
    uint32_t a;
    asm("{ .reg .u64 t; cvta.to.shared.u64 t, %1; cvt.u32.u64 %0, t; }" : "=r"(a) : "l"(p));
    return a;
}
__device__ __forceinline__ void cpasync16(uint32_t smem, const void* g) {
    asm volatile("cp.async.cg.shared.global [%0], [%1], 16;" :: "r"(smem), "l"(g));
}
__device__ __forceinline__ void cp_commit() { asm volatile("cp.async.commit_group;" ::: "memory"); }
template<int N> __device__ __forceinline__ void cp_wait() {
    asm volatile("cp.async.wait_group %0;" :: "n"(N) : "memory");
}
__device__ __forceinline__ void ldsm_x4(uint32_t* r, uint32_t addr) {
    asm volatile("ldmatrix.sync.aligned.m8n8.x4.shared.b16 {%0,%1,%2,%3}, [%4];"
                 : "=r"(r[0]), "=r"(r[1]), "=r"(r[2]), "=r"(r[3]) : "r"(addr));
}
__device__ __forceinline__ void ldsm_x4_t(uint32_t* r, uint32_t addr) {
    asm volatile("ldmatrix.sync.aligned.m8n8.x4.trans.shared.b16 {%0,%1,%2,%3}, [%4];"
                 : "=r"(r[0]), "=r"(r[1]), "=r"(r[2]), "=r"(r[3]) : "r"(addr));
}
__device__ __forceinline__ void mma16816(float* d, const uint32_t* a, const uint32_t* b) {
    asm volatile(
        "mma.sync.aligned.m16n8k16.row.col.f32.f16.f16.f32 "
        "{%0,%1,%2,%3}, {%4,%5,%6,%7}, {%8,%9}, {%0,%1,%2,%3};"
        : "+f"(d[0]), "+f"(d[1]), "+f"(d[2]), "+f"(d[3])
        : "r"(a[0]), "r"(a[1]), "r"(a[2]), "r"(a[3]), "r"(b[0]), "r"(b[1]));
}

__device__ __forceinline__ uint32_t pack_h2(__half a, __half b) {
    return (uint32_t)__half_as_ushort(a) | ((uint32_t)__half_as_ushort(b) << 16);
}
__device__ __forceinline__ uint32_t pack_rn2(float a, float b) {
    __half2 h = __floats2half2_rn(a, b);
    return *(uint32_t*)&h;
}
// split two floats into hi/lo packed fp16x2 (hi+lo represents input to ~2^-22)
__device__ __forceinline__ void hsplit2(uint32_t& hi, uint32_t& lo, float a, float b) {
    __half ah = __float2half_rn(a);
    __half bh = __float2half_rn(b);
    float ar = a - __half2float(ah);
    float br = b - __half2float(bh);
    hi = pack_h2(ah, bh);
    lo = pack_h2(__float2half_rn(ar), __float2half_rn(br));
}

// ---------------------------------------------------------------------------
// fp32 -> fp16 hi/lo split  and  fp32 -> fp16 round (elementwise)
// ---------------------------------------------------------------------------
__global__ __launch_bounds__(256) void split2h_kernel(const float* __restrict__ src,
                                                      __half* __restrict__ hi,
                                                      __half* __restrict__ lo,
                                                      int n4)
{
    int i = blockIdx.x * 256 + threadIdx.x;
    if (i >= n4) return;
    float4 v = ((const float4*)src)[i];
    uint32_t h0, l0, h1, l1;
    hsplit2(h0, l0, v.x, v.y);
    hsplit2(h1, l1, v.z, v.w);
    ((uint2*)hi)[i] = make_uint2(h0, h1);
    ((uint2*)lo)[i] = make_uint2(l0, l1);
}

__global__ __launch_bounds__(256) void roundh_kernel(const float* __restrict__ src,
                                                     __half* __restrict__ dst,
                                                     int n4)
{
    int i = blockIdx.x * 256 + threadIdx.x;
    if (i >= n4) return;
    float4 v = ((const float4*)src)[i];
    ((uint2*)dst)[i] = make_uint2(pack_rn2(v.x, v.y), pack_rn2(v.z, v.w));
}

// ---------------------------------------------------------------------------
// fp16 2-product GEMM: out[m,e] = sum_d (Ah+Al)[m,d] * B16[e,d]
// CTA tile 128x128, 8 warps (warp 32x64), KC=32, 3-stage pipeline, 2 CTAs/SM.
// mode 4: fused QKV (B spans 3 contiguous weight arrays; out by n-block:
//         0 -> g_q fp32, 1 -> g_k fp32, 2 -> g_v16 fp16), layout [B,H,S,HD].
// mode 3: plain fp32 rows to outPlain.
// ---------------------------------------------------------------------------
#define KC 32
#define NSG (DM / KC)          // 64
#define RS 80                  // smem row stride (32 fp16 = 64B + 16B pad)
#define ARR_BYTES (128 * RS)   // 10240
#define STG_BYTES (3 * ARR_BYTES)   // 30720: Ah, Al, B
#define GEMM_SMEM (3 * STG_BYTES)   // 92160

__device__ __forceinline__ void load_stage(uint32_t st,
                                           const __half* __restrict__ aH,
                                           const __half* __restrict__ aL,
                                           const __half* __restrict__ bH,
                                           int m0, int n0, int k0, int tid)
{
#pragma unroll
    for (int it = 0; it < 6; it++) {
        int c   = it * 256 + tid;
        int arr = c >> 9;
        int idx = c & 511;
        int row = idx >> 2;
        int ch  = idx & 3;
        uint32_t off = st + (uint32_t)arr * ARR_BYTES + (uint32_t)row * RS + ch * 16;
        const __half* src = (arr == 0) ? aH : (arr == 1) ? aL : bH;
        int grow = (arr < 2) ? (m0 + row) : (n0 + row);
        cpasync16(off, src + (size_t)grow * DM + k0 + ch * 8);
    }
}

__global__ __launch_bounds__(256, 2) void gemm_tc(const __half* __restrict__ aH,
                                                  const __half* __restrict__ aL,
                                                  const __half* __restrict__ bH,
                                                  float* __restrict__ outPlain,
                                                  int mode)
{
    extern __shared__ char smem_raw[];
    const uint32_t sb = smem_u32(smem_raw);
    const int tid  = threadIdx.x;
    const int lane = tid & 31;
    const int wid  = tid >> 5;
    const int m0 = blockIdx.y * 128;
    const int n0 = blockIdx.x * 128;
    const int m0w = (wid >> 1) * 32;
    const int n0w = (wid & 1) * 64;

    float acc[2][8][4];
#pragma unroll
    for (int i = 0; i < 2; i++)
#pragma unroll
        for (int j = 0; j < 8; j++)
#pragma unroll
            for (int f = 0; f < 4; f++) acc[i][j][f] = 0.0f;

    uint32_t aRow[2], bRow[4];
#pragma unroll
    for (int i = 0; i < 2; i++)
        aRow[i] = (uint32_t)(m0w + i * 16 + (lane & 15)) * RS + (((uint32_t)lane >> 4) << 4);
#pragma unroll
    for (int jj = 0; jj < 4; jj++)
        bRow[jj] = (uint32_t)(n0w + jj * 16 + (((uint32_t)lane >> 4) << 3) + (lane & 7)) * RS
                 + ((((uint32_t)lane >> 3) & 1) << 4);

    load_stage(sb + 0 * STG_BYTES, aH, aL, bH, m0, n0, 0,  tid); cp_commit();
    load_stage(sb + 1 * STG_BYTES, aH, aL, bH, m0, n0, KC, tid); cp_commit();

    int cur = 0, nxt = 2;
    for (int s = 0; s < NSG; s++) {
        cp_wait<1>();
        __syncthreads();

        if (s + 2 < NSG)
            load_stage(sb + (uint32_t)nxt * STG_BYTES, aH, aL, bH, m0, n0, (s + 2) * KC, tid);
        cp_commit();

        const uint32_t st = sb + (uint32_t)cur * STG_BYTES;
#pragma unroll
        for (int ks = 0; ks < 2; ks++) {
            const uint32_t kb = (uint32_t)ks * 32;
            uint32_t ah_[2][4], al_[2][4], bh_[4][4];
#pragma unroll
            for (int i = 0; i < 2; i++) {
                ldsm_x4(ah_[i], st + aRow[i] + kb);
                ldsm_x4(al_[i], st + ARR_BYTES + aRow[i] + kb);
            }
#pragma unroll
            for (int jj = 0; jj < 4; jj++)
                ldsm_x4(bh_[jj], st + 2 * ARR_BYTES + bRow[jj] + kb);
#pragma unroll
            for (int i = 0; i < 2; i++)
#pragma unroll
                for (int jj = 0; jj < 4; jj++) {
                    mma16816(acc[i][2 * jj],     ah_[i], &bh_[jj][0]);
                    mma16816(acc[i][2 * jj + 1], ah_[i], &bh_[jj][2]);
                    mma16816(acc[i][2 * jj],     al_[i], &bh_[jj][0]);
                    mma16816(acc[i][2 * jj + 1], al_[i], &bh_[jj][2]);
                }
        }
        cur = (cur == 2) ? 0 : cur + 1;
        nxt = (nxt == 2) ? 0 : nxt + 1;
    }

    const int gid = lane >> 2;
    const int tig = lane & 3;
    const int nb = n0 >> 11;             // 0 q, 1 k, 2 v (mode 4)
    const int hh = (n0 >> 7) & (NH - 1);
    float* out = (mode == 3) ? outPlain : (nb == 0) ? g_q : g_k;

#pragma unroll
    for (int i = 0; i < 2; i++) {
        const int r0g = m0 + m0w + i * 16 + gid;
#pragma unroll
        for (int j = 0; j < 8; j++) {
            const int gcol = n0 + n0w + j * 8 + tig * 2;
            if (mode == 3) {
                *(float2*)(out + (size_t)r0g * DM + gcol) = make_float2(acc[i][j][0], acc[i][j][1]);
                *(float2*)(out + (size_t)(r0g + 8) * DM + gcol) = make_float2(acc[i][j][2], acc[i][j][3]);
            } else {
                const int d = gcol & (HD - 1);
                int b0b = r0g >> 11, s0s = r0g & (SQ - 1);
                size_t o0 = ((size_t)(b0b * NH + hh) * SQ + s0s) * HD + d;
                int r1g = r0g + 8;
                int b1b = r1g >> 11, s1s = r1g & (SQ - 1);
                size_t o1 = ((size_t)(b1b * NH + hh) * SQ + s1s) * HD + d;
                if (nb == 2) {
                    *(uint32_t*)(g_v16 + o0) = pack_rn2(acc[i][j][0], acc[i][j][1]);
                    *(uint32_t*)(g_v16 + o1) = pack_rn2(acc[i][j][2], acc[i][j][3]);
                } else {
                    *(float2*)(out + o0) = make_float2(acc[i][j][0], acc[i][j][1]);
                    *(float2*)(out + o1) = make_float2(acc[i][j][2], acc[i][j][3]);
                }
            }
        }
    }
}

// ---------------------------------------------------------------------------
// RoPE -> fp16: q scaled by 1/sqrt(HD), k plain
// ---------------------------------------------------------------------------
__global__ __launch_bounds__(256) void rope_h(const float* __restrict__ cs,
                                              const float* __restrict__ sn)
{
    const int idx = blockIdx.x * blockDim.x + threadIdx.x;
    const int d  = idx & 63;
    const int s  = (idx >> 6) & (SQ - 1);
    const int bh = idx >> 17;
    const size_t base = ((size_t)bh * SQ + s) * HD;
    const float c  = cs[s * 64 + d];
    const float si = sn[s * 64 + d];
    const float SCALE = 0.08838834764831845f;

    float q1 = g_q[base + d], q2 = g_q[base + d + 64];
    g_q16[base + d]      = __float2half_rn((q1 * c - q2 * si) * SCALE);
    g_q16[base + d + 64] = __float2half_rn((q1 * si + q2 * c) * SCALE);

    float k1 = g_k[base + d], k2 = g_k[base + d + 64];
    g_k16[base + d]      = __float2half_rn(k1 * c - k2 * si);
    g_k16[base + d + 64] = __float2half_rn(k1 * si + k2 * c);
}

// ---------------------------------------------------------------------------
// Tensor-core flash attention (fp16 single-product scores and PV)
// CTA: (b,h) x 128 q-rows; K/V in 64-row tiles, double buffered; 2 CTAs/SM.
// ---------------------------------------------------------------------------
#define FRS 272u
#define QARR 34816u            // 128*272
#define KARR 17408u            // 64*272
#define FST  (2u*KARR)         // stage: k16, v16 = 34816
#define FLASH_SMEM (QARR + 2u*FST)   // 104448

__device__ __forceinline__ void load_kv(uint32_t st, size_t gbase, int tid)
{
#pragma unroll
    for (int it = 0; it < 8; it++) {
        int idx = it * 256 + tid;
        int arr = idx >> 10;            // 0 k16, 1 v16
        int r   = (idx >> 4) & 63;
        int c   = idx & 15;
        const __half* src = arr ? g_v16 : g_k16;
        cpasync16(st + (uint32_t)arr * KARR + (uint32_t)r * FRS + c * 16,
                  src + gbase + (size_t)r * HD + c * 8);
    }
}

__global__ __launch_bounds__(256, 2) void flash_tc()
{
    extern __shared__ char smem_raw[];
    const uint32_t sb = smem_u32(smem_raw);
    const int tid  = threadIdx.x;
    const int lane = tid & 31;
    const int wid  = tid >> 5;
    const int bh = blockIdx.y;
    const int q0 = blockIdx.x * 128;
    const size_t qg  = ((size_t)bh * SQ + q0) * HD;
    const size_t kvg = (size_t)bh * SQ * HD;

    // stage Q (single fp16) + first two KV tiles
#pragma unroll
    for (int it = 0; it < 8; it++) {
        int idx = it * 256 + tid;
        int r   = idx >> 4;
        int c   = idx & 15;
        cpasync16(sb + (uint32_t)r * FRS + c * 16, g_q16 + qg + (size_t)r * HD + c * 8);
    }
    load_kv(sb + QARR, kvg, tid);
    cp_commit();
    load_kv(sb + QARR + FST, kvg + (size_t)64 * HD, tid);
    cp_commit();

    const uint32_t aRowQ = (uint32_t)(wid * 16 + (lane & 15)) * FRS + (((uint32_t)lane >> 4) << 4);
    uint32_t bRowK[4];
#pragma unroll
    for (int jj = 0; jj < 4; jj++)
        bRowK[jj] = (uint32_t)(jj * 16 + (((uint32_t)lane >> 4) << 3) + (lane & 7)) * FRS
                  + ((((uint32_t)lane >> 3) & 1) << 4);
    const uint32_t vRowBase = (uint32_t)((lane & 7) + (((uint32_t)lane >> 3) & 1) * 8) * FRS
                            + (((uint32_t)lane >> 4) << 4);

    float oacc[16][4];
#pragma unroll
    for (int f = 0; f < 16; f++)
#pragma unroll
        for (int e = 0; e < 4; e++) oacc[f][e] = 0.0f;
    float m0 = -1e30f, m1 = -1e30f, l0 = 0.0f, l1 = 0.0f;

    for (int s = 0; s < SQ / 64; s++) {
        cp_wait<1>();
        __syncthreads();
        const uint32_t st = sb + QARR + (uint32_t)(s & 1) * FST;

        // scores: S[16,64] = Q . K^T (single product)
        float sc[8][4];
#pragma unroll
        for (int f = 0; f < 8; f++)
#pragma unroll
            for (int e = 0; e < 4; e++) sc[f][e] = 0.0f;

#pragma unroll
        for (int ks = 0; ks < 8; ks++) {
            const uint32_t kb = (uint32_t)ks * 32;
            uint32_t qh_[4];
            ldsm_x4(qh_, sb + aRowQ + kb);
#pragma unroll
            for (int jj = 0; jj < 4; jj++) {
                uint32_t kh_[4];
                ldsm_x4(kh_, st + bRowK[jj] + kb);
                mma16816(sc[2 * jj],     qh_, &kh_[0]);
                mma16816(sc[2 * jj + 1], qh_, &kh_[2]);
            }
        }

        // online softmax
        float mx0 = -1e30f, mx1 = -1e30f;
#pragma unroll
        for (int f = 0; f < 8; f++) {
            mx0 = fmaxf(mx0, fmaxf(sc[f][0], sc[f][1]));
            mx1 = fmaxf(mx1, fmaxf(sc[f][2], sc[f][3]));
        }
        mx0 = fmaxf(mx0, __shfl_xor_sync(0xffffffffu, mx0, 1));
        mx0 = fmaxf(mx0, __shfl_xor_sync(0xffffffffu, mx0, 2));
        mx1 = fmaxf(mx1, __shfl_xor_sync(0xffffffffu, mx1, 1));
        mx1 = fmaxf(mx1, __shfl_xor_sync(0xffffffffu, mx1, 2));
        const float mn0 = fmaxf(m0, mx0), mn1 = fmaxf(m1, mx1);
        const float al0 = __expf(m0 - mn0), al1 = __expf(m1 - mn1);
        float rs0 = 0.0f, rs1 = 0.0f;
#pragma unroll
        for (int f = 0; f < 8; f++) {
            sc[f][0] = __expf(sc[f][0] - mn0);
            sc[f][1] = __expf(sc[f][1] - mn0);
            sc[f][2] = __expf(sc[f][2] - mn1);
            sc[f][3] = __expf(sc[f][3] - mn1);
            rs0 += sc[f][0] + sc[f][1];
            rs1 += sc[f][2] + sc[f][3];
        }
        rs0 += __shfl_xor_sync(0xffffffffu, rs0, 1);
        rs0 += __shfl_xor_sync(0xffffffffu, rs0, 2);
        rs1 += __shfl_xor_sync(0xffffffffu, rs1, 1);
        rs1 += __shfl_xor_sync(0xffffffffu, rs1, 2);
        l0 = l0 * al0 + rs0;
        l1 = l1 * al1 + rs1;
        m0 = mn0; m1 = mn1;
#pragma unroll
        for (int f = 0; f < 16; f++) {
            oacc[f][0] *= al0; oacc[f][1] *= al0;
            oacc[f][2] *= al1; oacc[f][3] *= al1;
        }

        // PV: O[16,128] += P . V (single product)
#pragma unroll
        for (int t = 0; t < 4; t++) {
            uint32_t ph[4];
            ph[0] = pack_rn2(sc[2 * t][0],     sc[2 * t][1]);
            ph[1] = pack_rn2(sc[2 * t][2],     sc[2 * t][3]);
            ph[2] = pack_rn2(sc[2 * t + 1][0], sc[2 * t + 1][1]);
            ph[3] = pack_rn2(sc[2 * t + 1][2], sc[2 * t + 1][3]);
            const uint32_t vb = vRowBase + (uint32_t)t * 16 * FRS;
#pragma unroll
            for (int dj = 0; dj < 8; dj++) {
                uint32_t vh_[4];
                ldsm_x4_t(vh_, st + KARR + vb + dj * 32);
                mma16816(oacc[2 * dj],     ph, &vh_[0]);
                mma16816(oacc[2 * dj + 1], ph, &vh_[2]);
            }
        }

        __syncthreads();
        if (s + 2 < SQ / 64)
            load_kv(sb + QARR + (uint32_t)(s & 1) * FST, kvg + (size_t)(s + 2) * 64 * HD, tid);
        cp_commit();
    }

    // epilogue: normalize, split to fp16 hi/lo into g_xh/g_xl (Wo A-operand)
    const float inv0 = 1.0f / l0, inv1 = 1.0f / l1;
    const int g  = lane >> 2;
    const int c2 = (lane & 3) * 2;
    const int b = bh >> 4, h = bh & (NH - 1);
    const int rowg = q0 + wid * 16 + g;
    const size_t base0 = ((size_t)(b * SQ) + rowg) * DM + h * HD;
    const size_t base1 = base0 + (size_t)8 * DM;
#pragma unroll
    for (int f = 0; f < 16; f++) {
        const int col = f * 8 + c2;
        uint32_t h0, l0p, h1, l1p;
        hsplit2(h0, l0p, oacc[f][0] * inv0, oacc[f][1] * inv0);
        hsplit2(h1, l1p, oacc[f][2] * inv1, oacc[f][3] * inv1);
        *(uint32_t*)(g_xh + base0 + col) = h0;
        *(uint32_t*)(g_xl + base0 + col) = l0p;
        *(uint32_t*)(g_xh + base1 + col) = h1;
        *(uint32_t*)(g_xl + base1 + col) = l1p;
    }
}

// ---------------------------------------------------------------------------
extern "C" void kernel_launch(void* const* d_in, const int* in_sizes, int n_in,
                              void* d_out, int out_size)
{
    (void)in_sizes; (void)n_in; (void)out_size;
    const float* x    = (const float*)d_in[0];
    const float* cosp = (const float*)d_in[1];
    const float* sinp = (const float*)d_in[2];
    const float* Wq   = (const float*)d_in[3];
    const float* Wk   = (const float*)d_in[4];
    const float* Wv   = (const float*)d_in[5];
    const float* Wo   = (const float*)d_in[6];
    float* out = (float*)d_out;

    void *pxh, *pxl, *pw;
    cudaGetSymbolAddress(&pxh, g_xh);
    cudaGetSymbolAddress(&pxl, g_xl);
    cudaGetSymbolAddress(&pw,  g_w16);
    __half* xh  = (__half*)pxh;
    __half* xl  = (__half*)pxl;
    __half* w16 = (__half*)pw;

    const int n4x = MT * DM / 4;
    const int n4w = DM * DM / 4;

    cudaFuncSetAttribute(gemm_tc, cudaFuncAttributeMaxDynamicSharedMemorySize, GEMM_SMEM);
    cudaFuncSetAttribute(flash_tc, cudaFuncAttributeMaxDynamicSharedMemorySize, (int)FLASH_SMEM);

    // 1. precision prep
    split2h_kernel<<<n4x / 256, 256>>>(x, xh, xl, n4x);
    roundh_kernel<<<n4w / 256, 256>>>(Wq, w16 + 0 * DMDM, n4w);
    roundh_kernel<<<n4w / 256, 256>>>(Wk, w16 + 1 * DMDM, n4w);
    roundh_kernel<<<n4w / 256, 256>>>(Wv, w16 + 2 * DMDM, n4w);
    roundh_kernel<<<n4w / 256, 256>>>(Wo, w16 + 3 * DMDM, n4w);

    // 2. fused QKV projection (q,k -> fp32 for RoPE; v -> fp16 directly)
    gemm_tc<<<dim3(3 * DM / 128, MT / 128), 256, GEMM_SMEM>>>(xh, xl, w16, nullptr, 4);

    // 3. RoPE -> fp16 (q pre-scaled by 1/sqrt(HD))
    rope_h<<<(NB * NH * SQ * 64) / 256, 256>>>(cosp, sinp);

    // 4. flash attention -> writes attn hi/lo into xh/xl
    flash_tc<<<dim3(SQ / 128, NB * NH), 256, FLASH_SMEM>>>();

    // 5. output projection
    gemm_tc<<<dim3(DM / 128, MT / 128), 256, GEMM_SMEM>>>(xh, xl, w16 + 3 * DMDM, out, 3);
}

// round 7
// speedup vs baseline: 8.7137x; 1.4895x over previous
#include <cuda_runtime.h>
#include <cuda_fp16.h>
#include <cstdint>

#define DM 2048
#define NH 16
#define HD 128
#define NB 4
#define SQ 2048
#define MT (NB*SQ)   // 8192 rows
#define DMDM ((size_t)DM*DM)

// ---------------------------------------------------------------------------
// Scratch (device globals)
// ---------------------------------------------------------------------------
__device__ float g_q[(size_t)NB*NH*SQ*HD];
__device__ float g_k[(size_t)NB*NH*SQ*HD];

__device__ __half g_q16[(size_t)NB*NH*SQ*HD];
__device__ __half g_k16[(size_t)NB*NH*SQ*HD];
__device__ __half g_v16[(size_t)NB*NH*SQ*HD];

__device__ __half g_a16[(size_t)MT*DM];      // A operand: x16, then attn16
__device__ __half g_w16[(size_t)4*DM*DM];

// ---------------------------------------------------------------------------
// Baseline-PTX helpers
// ---------------------------------------------------------------------------
__device__ __forceinline__ uint32_t smem_u32(const void* p) {
    uint32_t a;
    asm("{ .reg .u64 t; cvta.to.shared.u64 t, %1; cvt.u32.u64 %0, t; }" : "=r"(a) : "l"(p));
    return a;
}
__device__ __forceinline__ void cpasync16(uint32_t smem, const void* g) {
    asm volatile("cp.async.cg.shared.global [%0], [%1], 16;" :: "r"(smem), "l"(g));
}
__device__ __forceinline__ void cp_commit() { asm volatile("cp.async.commit_group;" ::: "memory"); }
template<int N> __device__ __forceinline__ void cp_wait() {
    asm volatile("cp.async.wait_group %0;" :: "n"(N) : "memory");
}
__device__ __forceinline__ void ldsm_x4(uint32_t* r, uint32_t addr) {
    asm volatile("ldmatrix.sync.aligned.m8n8.x4.shared.b16 {%0,%1,%2,%3}, [%4];"
                 : "=r"(r[0]), "=r"(r[1]), "=r"(r[2]), "=r"(r[3]) : "r"(addr));
}
__device__ __forceinline__ void ldsm_x4_t(uint32_t* r, uint32_t addr) {
    asm volatile("ldmatrix.sync.aligned.m8n8.x4.trans.shared.b16 {%0,%1,%2,%3}, [%4];"
                 : "=r"(r[0]), "=r"(r[1]), "=r"(r[2]), "=r"(r[3]) : "r"(addr));
}
__device__ __forceinline__ void mma16816(float* d, const uint32_t* a, const uint32_t* b) {
    asm volatile(
        "mma.sync.aligned.m16n8k16.row.col.f32.f16.f16.f32 "
        "{%0,%1,%2,%3}, {%4,%5,%6,%7}, {%8,%9}, {%0,%1,%2,%3};"
        : "+f"(d[0]), "+f"(d[1]), "+f"(d[2]), "+f"(d[3])
        : "r"(a[0]), "r"(a[1]), "r"(a[2]), "r"(a[3]), "r"(b[0]), "r"(b[1]));
}

__device__ __forceinline__ uint32_t pack_rn2(float a, float b) {
    __half2 h = __floats2half2_rn(a, b);
    return *(uint32_t*)&h;
}

// ---------------------------------------------------------------------------
// fp32 -> fp16 round (elementwise)
// ---------------------------------------------------------------------------
__global__ __launch_bounds__(256) void roundh_kernel(const float* __restrict__ src,
                                                     __half* __restrict__ dst,
                                                     int n4)
{
    int i = blockIdx.x * 256 + threadIdx.x;
    if (i >= n4) return;
    float4 v = ((const float4*)src)[i];
    ((uint2*)dst)[i] = make_uint2(pack_rn2(v.x, v.y), pack_rn2(v.z, v.w));
}

// ---------------------------------------------------------------------------
// fp16 single-product GEMM: out[m,e] = sum_d A16[m,d] * B16[e,d]
// CTA tile 128x128, 8 warps (warp 32x64), KC=32, 4-stage pipeline, 2 CTAs/SM.
// mode 4: fused QKV (out by n-block: 0 -> g_q fp32, 1 -> g_k fp32,
//         2 -> g_v16 fp16), layout [B,H,S,HD]. mode 3: plain fp32 rows.
// ---------------------------------------------------------------------------
#define KC 32
#define NSG (DM / KC)          // 64
#define RS 80                  // smem row stride (32 fp16 = 64B + 16B pad)
#define ARR_BYTES (128 * RS)   // 10240
#define STG_BYTES (2 * ARR_BYTES)   // 20480: A, B
#define NSTAGE 4
#define GEMM_SMEM (NSTAGE * STG_BYTES)   // 81920

__device__ __forceinline__ void load_stage(uint32_t st,
                                           const __half* __restrict__ a16,
                                           const __half* __restrict__ b16,
                                           int m0, int n0, int k0, int tid)
{
    // 2 arrays x 128 rows x 4 chunks(16B) = 1024 chunks; 4 per thread
#pragma unroll
    for (int it = 0; it < 4; it++) {
        int c   = it * 256 + tid;
        int arr = c >> 9;
        int idx = c & 511;
        int row = idx >> 2;
        int ch  = idx & 3;
        uint32_t off = st + (uint32_t)arr * ARR_BYTES + (uint32_t)row * RS + ch * 16;
        const __half* src = arr ? b16 : a16;
        int grow = arr ? (n0 + row) : (m0 + row);
        cpasync16(off, src + (size_t)grow * DM + k0 + ch * 8);
    }
}

__global__ __launch_bounds__(256, 2) void gemm_tc(const __half* __restrict__ a16,
                                                  const __half* __restrict__ b16,
                                                  float* __restrict__ outPlain,
                                                  int mode)
{
    extern __shared__ char smem_raw[];
    const uint32_t sb = smem_u32(smem_raw);
    const int tid  = threadIdx.x;
    const int lane = tid & 31;
    const int wid  = tid >> 5;
    const int m0 = blockIdx.y * 128;
    const int n0 = blockIdx.x * 128;
    const int m0w = (wid >> 1) * 32;
    const int n0w = (wid & 1) * 64;

    float acc[2][8][4];
#pragma unroll
    for (int i = 0; i < 2; i++)
#pragma unroll
        for (int j = 0; j < 8; j++)
#pragma unroll
            for (int f = 0; f < 4; f++) acc[i][j][f] = 0.0f;

    uint32_t aRow[2], bRow[4];
#pragma unroll
    for (int i = 0; i < 2; i++)
        aRow[i] = (uint32_t)(m0w + i * 16 + (lane & 15)) * RS + (((uint32_t)lane >> 4) << 4);
#pragma unroll
    for (int jj = 0; jj < 4; jj++)
        bRow[jj] = (uint32_t)(n0w + jj * 16 + (((uint32_t)lane >> 4) << 3) + (lane & 7)) * RS
                 + ((((uint32_t)lane >> 3) & 1) << 4);

    // prologue: stages 0..2
#pragma unroll
    for (int s = 0; s < 3; s++) {
        load_stage(sb + (uint32_t)s * STG_BYTES, a16, b16, m0, n0, s * KC, tid);
        cp_commit();
    }

    for (int s = 0; s < NSG; s++) {
        cp_wait<2>();
        __syncthreads();

        if (s + 3 < NSG)
            load_stage(sb + (uint32_t)((s + 3) & 3) * STG_BYTES, a16, b16, m0, n0, (s + 3) * KC, tid);
        cp_commit();

        const uint32_t st = sb + (uint32_t)(s & 3) * STG_BYTES;
#pragma unroll
        for (int ks = 0; ks < 2; ks++) {
            const uint32_t kb = (uint32_t)ks * 32;
            uint32_t a_[2][4], b_[4][4];
#pragma unroll
            for (int i = 0; i < 2; i++)
                ldsm_x4(a_[i], st + aRow[i] + kb);
#pragma unroll
            for (int jj = 0; jj < 4; jj++)
                ldsm_x4(b_[jj], st + ARR_BYTES + bRow[jj] + kb);
#pragma unroll
            for (int i = 0; i < 2; i++)
#pragma unroll
                for (int jj = 0; jj < 4; jj++) {
                    mma16816(acc[i][2 * jj],     a_[i], &b_[jj][0]);
                    mma16816(acc[i][2 * jj + 1], a_[i], &b_[jj][2]);
                }
        }
    }

    const int gid = lane >> 2;
    const int tig = lane & 3;
    const int nb = n0 >> 11;             // 0 q, 1 k, 2 v (mode 4)
    const int hh = (n0 >> 7) & (NH - 1);
    float* out = (mode == 3) ? outPlain : (nb == 0) ? g_q : g_k;

#pragma unroll
    for (int i = 0; i < 2; i++) {
        const int r0g = m0 + m0w + i * 16 + gid;
#pragma unroll
        for (int j = 0; j < 8; j++) {
            const int gcol = n0 + n0w + j * 8 + tig * 2;
            if (mode == 3) {
                *(float2*)(out + (size_t)r0g * DM + gcol) = make_float2(acc[i][j][0], acc[i][j][1]);
                *(float2*)(out + (size_t)(r0g + 8) * DM + gcol) = make_float2(acc[i][j][2], acc[i][j][3]);
            } else {
                const int d = gcol & (HD - 1);
                int b0b = r0g >> 11, s0s = r0g & (SQ - 1);
                size_t o0 = ((size_t)(b0b * NH + hh) * SQ + s0s) * HD + d;
                int r1g = r0g + 8;
                int b1b = r1g >> 11, s1s = r1g & (SQ - 1);
                size_t o1 = ((size_t)(b1b * NH + hh) * SQ + s1s) * HD + d;
                if (nb == 2) {
                    *(uint32_t*)(g_v16 + o0) = pack_rn2(acc[i][j][0], acc[i][j][1]);
                    *(uint32_t*)(g_v16 + o1) = pack_rn2(acc[i][j][2], acc[i][j][3]);
                } else {
                    *(float2*)(out + o0) = make_float2(acc[i][j][0], acc[i][j][1]);
                    *(float2*)(out + o1) = make_float2(acc[i][j][2], acc[i][j][3]);
                }
            }
        }
    }
}

// ---------------------------------------------------------------------------
// RoPE -> fp16: q scaled by 1/sqrt(HD), k plain
// ---------------------------------------------------------------------------
__global__ __launch_bounds__(256) void rope_h(const float* __restrict__ cs,
                                              const float* __restrict__ sn)
{
    const int idx = blockIdx.x * blockDim.x + threadIdx.x;
    const int d  = idx & 63;
    const int s  = (idx >> 6) & (SQ - 1);
    const int bh = idx >> 17;
    const size_t base = ((size_t)bh * SQ + s) * HD;
    const float c  = cs[s * 64 + d];
    const float si = sn[s * 64 + d];
    const float SCALE = 0.08838834764831845f;

    float q1 = g_q[base + d], q2 = g_q[base + d + 64];
    g_q16[base + d]      = __float2half_rn((q1 * c - q2 * si) * SCALE);
    g_q16[base + d + 64] = __float2half_rn((q1 * si + q2 * c) * SCALE);

    float k1 = g_k[base + d], k2 = g_k[base + d + 64];
    g_k16[base + d]      = __float2half_rn(k1 * c - k2 * si);
    g_k16[base + d + 64] = __float2half_rn(k1 * si + k2 * c);
}

// ---------------------------------------------------------------------------
// Tensor-core flash attention (fp16 single-product)
// CTA: (b,h) x 128 q-rows; K/V in 64-row tiles, double buffered; 2 CTAs/SM.
// ---------------------------------------------------------------------------
#define FRS 272u
#define QARR 34816u            // 128*272
#define KARR 17408u            // 64*272
#define FST  (2u*KARR)         // stage: k16, v16 = 34816
#define FLASH_SMEM (QARR + 2u*FST)   // 104448

__device__ __forceinline__ void load_kv(uint32_t st, size_t gbase, int tid)
{
#pragma unroll
    for (int it = 0; it < 8; it++) {
        int idx = it * 256 + tid;
        int arr = idx >> 10;            // 0 k16, 1 v16
        int r   = (idx >> 4) & 63;
        int c   = idx & 15;
        const __half* src = arr ? g_v16 : g_k16;
        cpasync16(st + (uint32_t)arr * KARR + (uint32_t)r * FRS + c * 16,
                  src + gbase + (size_t)r * HD + c * 8);
    }
}

__global__ __launch_bounds__(256, 2) void flash_tc()
{
    extern __shared__ char smem_raw[];
    const uint32_t sb = smem_u32(smem_raw);
    const int tid  = threadIdx.x;
    const int lane = tid & 31;
    const int wid  = tid >> 5;
    const int bh = blockIdx.y;
    const int q0 = blockIdx.x * 128;
    const size_t qg  = ((size_t)bh * SQ + q0) * HD;
    const size_t kvg = (size_t)bh * SQ * HD;

    // stage Q + first two KV tiles
#pragma unroll
    for (int it = 0; it < 8; it++) {
        int idx = it * 256 + tid;
        int r   = idx >> 4;
        int c   = idx & 15;
        cpasync16(sb + (uint32_t)r * FRS + c * 16, g_q16 + qg + (size_t)r * HD + c * 8);
    }
    load_kv(sb + QARR, kvg, tid);
    cp_commit();
    load_kv(sb + QARR + FST, kvg + (size_t)64 * HD, tid);
    cp_commit();

    const uint32_t aRowQ = (uint32_t)(wid * 16 + (lane & 15)) * FRS + (((uint32_t)lane >> 4) << 4);
    uint32_t bRowK[4];
#pragma unroll
    for (int jj = 0; jj < 4; jj++)
        bRowK[jj] = (uint32_t)(jj * 16 + (((uint32_t)lane >> 4) << 3) + (lane & 7)) * FRS
                  + ((((uint32_t)lane >> 3) & 1) << 4);
    const uint32_t vRowBase = (uint32_t)((lane & 7) + (((uint32_t)lane >> 3) & 1) * 8) * FRS
                            + (((uint32_t)lane >> 4) << 4);

    float oacc[16][4];
#pragma unroll
    for (int f = 0; f < 16; f++)
#pragma unroll
        for (int e = 0; e < 4; e++) oacc[f][e] = 0.0f;
    float m0 = -1e30f, m1 = -1e30f, l0 = 0.0f, l1 = 0.0f;

    for (int s = 0; s < SQ / 64; s++) {
        cp_wait<1>();
        __syncthreads();
        const uint32_t st = sb + QARR + (uint32_t)(s & 1) * FST;

        // scores: S[16,64] = Q . K^T
        float sc[8][4];
#pragma unroll
        for (int f = 0; f < 8; f++)
#pragma unroll
            for (int e = 0; e < 4; e++) sc[f][e] = 0.0f;

#pragma unroll
        for (int ks = 0; ks < 8; ks++) {
            const uint32_t kb = (uint32_t)ks * 32;
            uint32_t qh_[4];
            ldsm_x4(qh_, sb + aRowQ + kb);
#pragma unroll
            for (int jj = 0; jj < 4; jj++) {
                uint32_t kh_[4];
                ldsm_x4(kh_, st + bRowK[jj] + kb);
                mma16816(sc[2 * jj],     qh_, &kh_[0]);
                mma16816(sc[2 * jj + 1], qh_, &kh_[2]);
            }
        }

        // online softmax
        float mx0 = -1e30f, mx1 = -1e30f;
#pragma unroll
        for (int f = 0; f < 8; f++) {
            mx0 = fmaxf(mx0, fmaxf(sc[f][0], sc[f][1]));
            mx1 = fmaxf(mx1, fmaxf(sc[f][2], sc[f][3]));
        }
        mx0 = fmaxf(mx0, __shfl_xor_sync(0xffffffffu, mx0, 1));
        mx0 = fmaxf(mx0, __shfl_xor_sync(0xffffffffu, mx0, 2));
        mx1 = fmaxf(mx1, __shfl_xor_sync(0xffffffffu, mx1, 1));
        mx1 = fmaxf(mx1, __shfl_xor_sync(0xffffffffu, mx1, 2));
        const float mn0 = fmaxf(m0, mx0), mn1 = fmaxf(m1, mx1);
        const float al0 = __expf(m0 - mn0), al1 = __expf(m1 - mn1);
        float rs0 = 0.0f, rs1 = 0.0f;
#pragma unroll
        for (int f = 0; f < 8; f++) {
            sc[f][0] = __expf(sc[f][0] - mn0);
            sc[f][1] = __expf(sc[f][1] - mn0);
            sc[f][2] = __expf(sc[f][2] - mn1);
            sc[f][3] = __expf(sc[f][3] - mn1);
            rs0 += sc[f][0] + sc[f][1];
            rs1 += sc[f][2] + sc[f][3];
        }
        rs0 += __shfl_xor_sync(0xffffffffu, rs0, 1);
        rs0 += __shfl_xor_sync(0xffffffffu, rs0, 2);
        rs1 += __shfl_xor_sync(0xffffffffu, rs1, 1);
        rs1 += __shfl_xor_sync(0xffffffffu, rs1, 2);
        l0 = l0 * al0 + rs0;
        l1 = l1 * al1 + rs1;
        m0 = mn0; m1 = mn1;
#pragma unroll
        for (int f = 0; f < 16; f++) {
            oacc[f][0] *= al0; oacc[f][1] *= al0;
            oacc[f][2] *= al1; oacc[f][3] *= al1;
        }

        // PV: O[16,128] += P . V
#pragma unroll
        for (int t = 0; t < 4; t++) {
            uint32_t ph[4];
            ph[0] = pack_rn2(sc[2 * t][0],     sc[2 * t][1]);
            ph[1] = pack_rn2(sc[2 * t][2],     sc[2 * t][3]);
            ph[2] = pack_rn2(sc[2 * t + 1][0], sc[2 * t + 1][1]);
            ph[3] = pack_rn2(sc[2 * t + 1][2], sc[2 * t + 1][3]);
            const uint32_t vb = vRowBase + (uint32_t)t * 16 * FRS;
#pragma unroll
            for (int dj = 0; dj < 8; dj++) {
                uint32_t vh_[4];
                ldsm_x4_t(vh_, st + KARR + vb + dj * 32);
                mma16816(oacc[2 * dj],     ph, &vh_[0]);
                mma16816(oacc[2 * dj + 1], ph, &vh_[2]);
            }
        }

        __syncthreads();
        if (s + 2 < SQ / 64)
            load_kv(sb + QARR + (uint32_t)(s & 1) * FST, kvg + (size_t)(s + 2) * 64 * HD, tid);
        cp_commit();
    }

    // epilogue: normalize, write single fp16 attn into g_a16 (Wo A-operand)
    const float inv0 = 1.0f / l0, inv1 = 1.0f / l1;
    const int g  = lane >> 2;
    const int c2 = (lane & 3) * 2;
    const int b = bh >> 4, h = bh & (NH - 1);
    const int rowg = q0 + wid * 16 + g;
    const size_t base0 = ((size_t)(b * SQ) + rowg) * DM + h * HD;
    const size_t base1 = base0 + (size_t)8 * DM;
#pragma unroll
    for (int f = 0; f < 16; f++) {
        const int col = f * 8 + c2;
        *(uint32_t*)(g_a16 + base0 + col) = pack_rn2(oacc[f][0] * inv0, oacc[f][1] * inv0);
        *(uint32_t*)(g_a16 + base1 + col) = pack_rn2(oacc[f][2] * inv1, oacc[f][3] * inv1);
    }
}

// ---------------------------------------------------------------------------
extern "C" void kernel_launch(void* const* d_in, const int* in_sizes, int n_in,
                              void* d_out, int out_size)
{
    (void)in_sizes; (void)n_in; (void)out_size;
    const float* x    = (const float*)d_in[0];
    const float* cosp = (const float*)d_in[1];
    const float* sinp = (const float*)d_in[2];
    const float* Wq   = (const float*)d_in[3];
    const float* Wk   = (const float*)d_in[4];
    const float* Wv   = (const float*)d_in[5];
    const float* Wo   = (const float*)d_in[6];
    float* out = (float*)d_out;

    void *pa, *pw;
    cudaGetSymbolAddress(&pa, g_a16);
    cudaGetSymbolAddress(&pw, g_w16);
    __half* a16 = (__half*)pa;
    __half* w16 = (__half*)pw;

    const int n4x = MT * DM / 4;
    const int n4w = DM * DM / 4;

    cudaFuncSetAttribute(gemm_tc, cudaFuncAttributeMaxDynamicSharedMemorySize, GEMM_SMEM);
    cudaFuncSetAttribute(flash_tc, cudaFuncAttributeMaxDynamicSharedMemorySize, (int)FLASH_SMEM);

    // 1. precision prep: everything to single fp16
    roundh_kernel<<<n4x / 256, 256>>>(x,  a16, n4x);
    roundh_kernel<<<n4w / 256, 256>>>(Wq, w16 + 0 * DMDM, n4w);
    roundh_kernel<<<n4w / 256, 256>>>(Wk, w16 + 1 * DMDM, n4w);
    roundh_kernel<<<n4w / 256, 256>>>(Wv, w16 + 2 * DMDM, n4w);
    roundh_kernel<<<n4w / 256, 256>>>(Wo, w16 + 3 * DMDM, n4w);

    // 2. fused QKV projection (q,k -> fp32 for RoPE; v -> fp16 directly)
    gemm_tc<<<dim3(3 * DM / 128, MT / 128), 256, GEMM_SMEM>>>(a16, w16, nullptr, 4);

    // 3. RoPE -> fp16 (q pre-scaled by 1/sqrt(HD))
    rope_h<<<(NB * NH * SQ * 64) / 256, 256>>>(cosp, sinp);

    // 4. flash attention -> writes attn fp16 into a16
    flash_tc<<<dim3(SQ / 128, NB * NH), 256, FLASH_SMEM>>>();

    // 5. output projection
    gemm_tc<<<dim3(DM / 128, MT / 128), 256, GEMM_SMEM>>>(a16, w16 + 3 * DMDM, out, 3);
}